// round 1
// baseline (speedup 1.0000x reference)
#include <cuda_runtime.h>

#define NN 5120        // nodes
#define NE 163840      // edges
#define TBLD 256       // input feature dim
#define LAT 128        // latent dim
#define NG 64          // graphs
#define NNEU 80        // neurons per graph
#define N2 6400        // 80*80
#define H1 12800       // hidden dim

typedef unsigned long long ull;

// ---------------- device scratch (no allocation allowed) ----------------
__device__ int   g_deg[NN];
__device__ int   g_srclist[NN * 128];
__device__ float g_dinv[NN];
__device__ float g_h[NN * LAT];          // x @ Wg
__device__ float g_z[NN * LAT];          // relu(GCN out)
__device__ float g_gram[NG * N2];        // batched z z^T
__device__ float g_z2p[4ull * NG * H1];  // GEMM1 split-K partials
__device__ float g_z2[NG * H1];          // relu(G@W1 + b1)
__device__ float g_yp[8ull * NG * N2];   // GEMM2 split-K partials

// ---------------- packed f32x2 helpers ----------------
__device__ __forceinline__ ull pk2(float lo, float hi) {
    ull r; asm("mov.b64 %0, {%1, %2};" : "=l"(r) : "f"(lo), "f"(hi)); return r;
}
__device__ __forceinline__ void fma2(ull& d, ull a, ull b) {
    asm("fma.rn.f32x2 %0, %1, %2, %0;" : "+l"(d) : "l"(a), "l"(b));
}
__device__ __forceinline__ float2 upk2(ull v) {
    float2 r; asm("mov.b64 {%0, %1}, %2;" : "=f"(r.x), "=f"(r.y) : "l"(v)); return r;
}

// ---------------- small kernels ----------------
__global__ void k_zero() {
    int i = blockIdx.x * 256 + threadIdx.x;
    if (i < NN) g_deg[i] = 0;
}

__global__ void k_fill(const int* __restrict__ src, const int* __restrict__ dst) {
    int e = blockIdx.x * 256 + threadIdx.x;
    if (e >= NE) return;
    int d = dst[e];
    int slot = atomicAdd(&g_deg[d], 1);
    if (slot < 128) g_srclist[(d << 7) + slot] = src[e];
}

__global__ void k_dinv() {
    int i = blockIdx.x * 256 + threadIdx.x;
    if (i < NN) {
        int c = g_deg[i];
        g_dinv[i] = (c > 0) ? rsqrtf((float)c) : 0.0f;
    }
}

// One warp per node: agg = sum_e dinv[src]*h[src]; z = relu(dinv[node]*agg + bg)
__global__ void k_gather_z(const float* __restrict__ bg) {
    int w = (blockIdx.x * blockDim.x + threadIdx.x) >> 5;
    int lane = threadIdx.x & 31;
    if (w >= NN) return;
    int cnt = g_deg[w];
    if (cnt > 128) cnt = 128;
    const int* sl = g_srclist + (w << 7);
    float4 acc = make_float4(0.f, 0.f, 0.f, 0.f);
    #pragma unroll 4
    for (int e = 0; e < cnt; e++) {
        int s = sl[e];
        float wt = g_dinv[s];
        const float4 h4 = *(const float4*)&g_h[(s << 7) + (lane << 2)];
        acc.x += wt * h4.x; acc.y += wt * h4.y;
        acc.z += wt * h4.z; acc.w += wt * h4.w;
    }
    float dv = g_dinv[w];
    float4 bb = ((const float4*)bg)[lane];
    float4 z;
    z.x = fmaxf(dv * acc.x + bb.x, 0.f);
    z.y = fmaxf(dv * acc.y + bb.y, 0.f);
    z.z = fmaxf(dv * acc.z + bb.z, 0.f);
    z.w = fmaxf(dv * acc.w + bb.w, 0.f);
    *(float4*)&g_z[(w << 7) + (lane << 2)] = z;
}

// Per-graph Gram matrix: G[b][i*80+j] = dot(z_i, z_j). Transposed smem tile
// zt[k][node] -> j-direction reads are conflict-free (stride 5, coprime w/ 32).
__global__ void k_gram() {
    __shared__ float zt[128][81];
    const int b = blockIdx.x;
    const int tid = threadIdx.x;
    #pragma unroll
    for (int i = 0; i < 10; i++) {
        int f = tid + i * 256;         // 2560 float4 total
        int row = f >> 5, k4 = f & 31;
        float4 v = *(const float4*)&g_z[((b * NNEU + row) << 7) + (k4 << 2)];
        zt[k4 * 4 + 0][row] = v.x; zt[k4 * 4 + 1][row] = v.y;
        zt[k4 * 4 + 2][row] = v.z; zt[k4 * 4 + 3][row] = v.w;
    }
    __syncthreads();
    const int tx = tid & 15, ty = tid >> 4;
    const int i0 = ty * 5, j0 = tx * 5;
    float acc[5][5];
    #pragma unroll
    for (int i = 0; i < 5; i++)
        #pragma unroll
        for (int j = 0; j < 5; j++) acc[i][j] = 0.f;
    #pragma unroll 4
    for (int k = 0; k < 128; k++) {
        float a[5], c[5];
        #pragma unroll
        for (int u = 0; u < 5; u++) { a[u] = zt[k][i0 + u]; c[u] = zt[k][j0 + u]; }
        #pragma unroll
        for (int i = 0; i < 5; i++)
            #pragma unroll
            for (int j = 0; j < 5; j++) acc[i][j] += a[i] * c[j];
    }
    float* G = g_gram + b * N2;
    #pragma unroll
    for (int i = 0; i < 5; i++)
        #pragma unroll
        for (int j = 0; j < 5; j++)
            G[(i0 + i) * NNEU + j0 + j] = acc[i][j];
}

// ---------------- f32x2 SGEMM: C_slab[z] = A[mo:mo+64] @ B[k0:k0+kchunk] ----
// Block tile 64x128, 128 threads, 8x8 micro-tile, packed-pair accumulators.
__global__ __launch_bounds__(128) void k_sgemm(
    const float* __restrict__ A, const float* __restrict__ B,
    float* __restrict__ C, int M, int N, int K, int kchunk)
{
    __shared__ float As[2][16][64];
    __shared__ float Bs[2][16][128];
    const int tid = threadIdx.x;
    const int tx = tid & 15, ty = tid >> 4;
    const int no = blockIdx.x * 128;
    const int mo = blockIdx.y * 64;
    const int k0 = blockIdx.z * kchunk;
    const int niters = kchunk >> 4;
    const float* Ab = A + (size_t)mo * K + k0;
    const float* Bb = B + (size_t)k0 * N + no;

    const int am0 = tid >> 2, akq = tid & 3;   // A loader: m, k-quad
    const int bk0 = tid >> 5, bc4 = tid & 31;  // B loader: k, col-quad

    ull acc[8][4];
    #pragma unroll
    for (int m = 0; m < 8; m++)
        #pragma unroll
        for (int p = 0; p < 4; p++) acc[m][p] = 0ULL;

    // preload tile 0
    {
        #pragma unroll
        for (int i = 0; i < 2; i++) {
            float4 v = *(const float4*)(Ab + (size_t)(am0 + i * 32) * K + akq * 4);
            As[0][akq * 4 + 0][am0 + i * 32] = v.x;
            As[0][akq * 4 + 1][am0 + i * 32] = v.y;
            As[0][akq * 4 + 2][am0 + i * 32] = v.z;
            As[0][akq * 4 + 3][am0 + i * 32] = v.w;
        }
        #pragma unroll
        for (int i = 0; i < 4; i++) {
            float4 v = *(const float4*)(Bb + (size_t)(bk0 + i * 4) * N + bc4 * 4);
            *(float4*)&Bs[0][bk0 + i * 4][bc4 * 4] = v;
        }
    }
    __syncthreads();

    for (int it = 0; it < niters; it++) {
        const int buf = it & 1;
        float4 rA[2], rB[4];
        const bool more = (it + 1 < niters);
        if (more) {
            const float* Abn = Ab + (it + 1) * 16;
            #pragma unroll
            for (int i = 0; i < 2; i++)
                rA[i] = *(const float4*)(Abn + (size_t)(am0 + i * 32) * K + akq * 4);
            const float* Bbn = Bb + (size_t)(it + 1) * 16 * N;
            #pragma unroll
            for (int i = 0; i < 4; i++)
                rB[i] = *(const float4*)(Bbn + (size_t)(bk0 + i * 4) * N + bc4 * 4);
        }
        #pragma unroll
        for (int kk = 0; kk < 16; kk++) {
            float4 a0 = *(float4*)&As[buf][kk][ty * 8];
            float4 a1 = *(float4*)&As[buf][kk][ty * 8 + 4];
            float4 b0 = *(float4*)&Bs[buf][kk][tx * 8];
            float4 b1 = *(float4*)&Bs[buf][kk][tx * 8 + 4];
            ull bp[4] = { pk2(b0.x, b0.y), pk2(b0.z, b0.w),
                          pk2(b1.x, b1.y), pk2(b1.z, b1.w) };
            float am[8] = { a0.x, a0.y, a0.z, a0.w, a1.x, a1.y, a1.z, a1.w };
            #pragma unroll
            for (int m = 0; m < 8; m++) {
                ull ad = pk2(am[m], am[m]);
                #pragma unroll
                for (int p = 0; p < 4; p++) fma2(acc[m][p], ad, bp[p]);
            }
        }
        if (more) {
            const int nb = buf ^ 1;
            #pragma unroll
            for (int i = 0; i < 2; i++) {
                As[nb][akq * 4 + 0][am0 + i * 32] = rA[i].x;
                As[nb][akq * 4 + 1][am0 + i * 32] = rA[i].y;
                As[nb][akq * 4 + 2][am0 + i * 32] = rA[i].z;
                As[nb][akq * 4 + 3][am0 + i * 32] = rA[i].w;
            }
            #pragma unroll
            for (int i = 0; i < 4; i++)
                *(float4*)&Bs[nb][bk0 + i * 4][bc4 * 4] = rB[i];
        }
        __syncthreads();
    }

    float* Cb = C + ((size_t)blockIdx.z * M + mo) * N + no;
    #pragma unroll
    for (int m = 0; m < 8; m++) {
        int row = ty * 8 + m;
        float2 p0 = upk2(acc[m][0]), p1 = upk2(acc[m][1]);
        float2 p2 = upk2(acc[m][2]), p3 = upk2(acc[m][3]);
        float4 o0 = make_float4(p0.x, p0.y, p1.x, p1.y);
        float4 o1 = make_float4(p2.x, p2.y, p3.x, p3.y);
        *(float4*)(Cb + (size_t)row * N + tx * 8) = o0;
        *(float4*)(Cb + (size_t)row * N + tx * 8 + 4) = o1;
    }
}

// combine 4 GEMM1 partials + bias, relu
__global__ void k_relu_combine(const float* __restrict__ b1) {
    int i = blockIdx.x * 256 + threadIdx.x;      // float4 index < 204800
    const float4* P = (const float4*)g_z2p;
    float4 a = P[i];
    float4 t1 = P[204800 + i], t2 = P[409600 + i], t3 = P[614400 + i];
    a.x += t1.x + t2.x + t3.x; a.y += t1.y + t2.y + t3.y;
    a.z += t1.z + t2.z + t3.z; a.w += t1.w + t2.w + t3.w;
    float4 bb = ((const float4*)b1)[i % 3200];
    float4 o;
    o.x = fmaxf(a.x + bb.x, 0.f); o.y = fmaxf(a.y + bb.y, 0.f);
    o.z = fmaxf(a.z + bb.z, 0.f); o.w = fmaxf(a.w + bb.w, 0.f);
    ((float4*)g_z2)[i] = o;
}

// combine 8 GEMM2 partials + bias, sigmoid -> output
__global__ void k_sigmoid_combine(const float* __restrict__ b2, float* __restrict__ out) {
    int i = blockIdx.x * 256 + threadIdx.x;      // float4 index < 102400
    const float4* P = (const float4*)g_yp;
    float4 a = P[i];
    #pragma unroll
    for (int p = 1; p < 8; p++) {
        float4 t = P[p * 102400 + i];
        a.x += t.x; a.y += t.y; a.z += t.z; a.w += t.w;
    }
    float4 bb = ((const float4*)b2)[i % 1600];
    a.x = 1.f / (1.f + expf(-(a.x + bb.x)));
    a.y = 1.f / (1.f + expf(-(a.y + bb.y)));
    a.z = 1.f / (1.f + expf(-(a.z + bb.z)));
    a.w = 1.f / (1.f + expf(-(a.w + bb.w)));
    ((float4*)out)[i] = a;
}

// ---------------- launcher ----------------
extern "C" void kernel_launch(void* const* d_in, const int* in_sizes, int n_in,
                              void* d_out, int out_size) {
    (void)in_sizes; (void)n_in; (void)out_size;
    const float* x  = (const float*)d_in[0];
    const int*   ei = (const int*)  d_in[1];
    const float* Wg = (const float*)d_in[2];
    const float* bg = (const float*)d_in[3];
    const float* W1 = (const float*)d_in[4];
    const float* b1 = (const float*)d_in[5];
    const float* W2 = (const float*)d_in[6];
    const float* b2 = (const float*)d_in[7];
    float* out = (float*)d_out;

    float* d_h    = nullptr; cudaGetSymbolAddress((void**)&d_h,    g_h);
    float* d_gram = nullptr; cudaGetSymbolAddress((void**)&d_gram, g_gram);
    float* d_z2p  = nullptr; cudaGetSymbolAddress((void**)&d_z2p,  g_z2p);
    float* d_z2   = nullptr; cudaGetSymbolAddress((void**)&d_z2,   g_z2);
    float* d_yp   = nullptr; cudaGetSymbolAddress((void**)&d_yp,   g_yp);

    k_zero<<<20, 256>>>();
    k_fill<<<640, 256>>>(ei, ei + NE);
    k_dinv<<<20, 256>>>();
    // h = x @ Wg : M=5120, N=128, K=256, single k-chunk (direct store to slab 0)
    k_sgemm<<<dim3(1, 80, 1), 128>>>(x, Wg, d_h, NN, LAT, TBLD, TBLD);
    k_gather_z<<<640, 256>>>(bg);
    k_gram<<<NG, 256>>>();
    // GEMM1: [64,6400] @ [6400,12800], split-K 4
    k_sgemm<<<dim3(100, 1, 4), 128>>>(d_gram, W1, d_z2p, NG, H1, N2, 1600);
    k_relu_combine<<<800, 256>>>(b1);
    // GEMM2: [64,12800] @ [12800,6400], split-K 8
    k_sgemm<<<dim3(50, 1, 8), 128>>>(d_z2, W2, d_yp, NG, N2, H1, 1600);
    k_sigmoid_combine<<<400, 256>>>(b2, out);
}

// round 3
// speedup vs baseline: 2.2031x; 2.2031x over previous
#include <cuda_runtime.h>
#include <cstdint>

#define NN 5120
#define NE 163840
#define TBLD 256
#define LAT 128
#define NG 64
#define NNEU 80
#define N2 6400
#define H1 12800

// ---------------- device scratch ----------------
__device__ int   g_deg[NN];
__device__ int   g_srclist[NN * 128];
__device__ float g_dinv[NN];
__device__ float g_h[NN * LAT];
__device__ float g_z[NN * LAT];
__device__ float g_gram[NG * N2];
__device__ float g_z2p[4ull * NG * H1];   // GEMM1 split-K=4 partials
__device__ float g_z2[NG * H1];
__device__ float g_yp[8ull * NG * N2];    // GEMM2 split-K=8 partials

// ---------------- graph-side kernels (proven in R1) ----------------
__global__ void k_zero() {
    int i = blockIdx.x * 256 + threadIdx.x;
    if (i < NN) g_deg[i] = 0;
}

__global__ void k_fill(const int* __restrict__ src, const int* __restrict__ dst) {
    int e = blockIdx.x * 256 + threadIdx.x;
    if (e >= NE) return;
    int d = dst[e];
    int slot = atomicAdd(&g_deg[d], 1);
    if (slot < 128) g_srclist[(d << 7) + slot] = src[e];
}

__global__ void k_dinv() {
    int i = blockIdx.x * 256 + threadIdx.x;
    if (i < NN) {
        int c = g_deg[i];
        g_dinv[i] = (c > 0) ? rsqrtf((float)c) : 0.0f;
    }
}

__global__ void k_gather_z(const float* __restrict__ bg) {
    int w = (blockIdx.x * blockDim.x + threadIdx.x) >> 5;
    int lane = threadIdx.x & 31;
    if (w >= NN) return;
    int cnt = g_deg[w];
    if (cnt > 128) cnt = 128;
    const int* sl = g_srclist + (w << 7);
    float4 acc = make_float4(0.f, 0.f, 0.f, 0.f);
    #pragma unroll 4
    for (int e = 0; e < cnt; e++) {
        int s = sl[e];
        float wt = g_dinv[s];
        const float4 h4 = *(const float4*)&g_h[(s << 7) + (lane << 2)];
        acc.x += wt * h4.x; acc.y += wt * h4.y;
        acc.z += wt * h4.z; acc.w += wt * h4.w;
    }
    float dv = g_dinv[w];
    float4 bb = ((const float4*)bg)[lane];
    float4 z;
    z.x = fmaxf(dv * acc.x + bb.x, 0.f);
    z.y = fmaxf(dv * acc.y + bb.y, 0.f);
    z.z = fmaxf(dv * acc.z + bb.z, 0.f);
    z.w = fmaxf(dv * acc.w + bb.w, 0.f);
    *(float4*)&g_z[(w << 7) + (lane << 2)] = z;
}

__global__ void k_gram() {
    __shared__ float zt[128][81];
    const int b = blockIdx.x;
    const int tid = threadIdx.x;
    #pragma unroll
    for (int i = 0; i < 10; i++) {
        int f = tid + i * 256;
        int row = f >> 5, k4 = f & 31;
        float4 v = *(const float4*)&g_z[((b * NNEU + row) << 7) + (k4 << 2)];
        zt[k4 * 4 + 0][row] = v.x; zt[k4 * 4 + 1][row] = v.y;
        zt[k4 * 4 + 2][row] = v.z; zt[k4 * 4 + 3][row] = v.w;
    }
    __syncthreads();
    const int tx = tid & 15, ty = tid >> 4;
    const int i0 = ty * 5, j0 = tx * 5;
    float acc[5][5];
    #pragma unroll
    for (int i = 0; i < 5; i++)
        #pragma unroll
        for (int j = 0; j < 5; j++) acc[i][j] = 0.f;
    #pragma unroll 4
    for (int k = 0; k < 128; k++) {
        float a[5], c[5];
        #pragma unroll
        for (int u = 0; u < 5; u++) { a[u] = zt[k][i0 + u]; c[u] = zt[k][j0 + u]; }
        #pragma unroll
        for (int i = 0; i < 5; i++)
            #pragma unroll
            for (int j = 0; j < 5; j++) acc[i][j] += a[i] * c[j];
    }
    float* G = g_gram + b * N2;
    #pragma unroll
    for (int i = 0; i < 5; i++)
        #pragma unroll
        for (int j = 0; j < 5; j++)
            G[(i0 + i) * NNEU + j0 + j] = acc[i][j];
}

// ---------------- tf32 mma.sync GEMM ----------------
__device__ __forceinline__ uint32_t smem_u32(const void* p) {
    return (uint32_t)__cvta_generic_to_shared(p);
}
__device__ __forceinline__ void cpa16(uint32_t dst, const void* src) {
    asm volatile("cp.async.cg.shared.global [%0], [%1], 16;" :: "r"(dst), "l"(src));
}
__device__ __forceinline__ uint32_t ldsu(uint32_t addr) {
    uint32_t v; asm volatile("ld.shared.b32 %0, [%1];" : "=r"(v) : "r"(addr)); return v;
}
__device__ __forceinline__ void hmma(float* c, const uint32_t* a, uint32_t b0, uint32_t b1) {
    asm volatile(
        "mma.sync.aligned.m16n8k8.row.col.f32.tf32.tf32.f32 "
        "{%0,%1,%2,%3}, {%4,%5,%6,%7}, {%8,%9}, {%0,%1,%2,%3};"
        : "+f"(c[0]), "+f"(c[1]), "+f"(c[2]), "+f"(c[3])
        : "r"(a[0]), "r"(a[1]), "r"(a[2]), "r"(a[3]), "r"(b0), "r"(b1));
}

// Block tile: M=64 x N=64*NT, K-chunk=32, 8 warps (each: 4 m16-tiles x NT n8-tiles).
// A smem 64x36 (pad), B smem 32x(64*NT+4) (pad) -> fragment loads conflict-free.
template<int NT>
__global__ __launch_bounds__(256, 2) void k_tgemm(
    const float* __restrict__ A, const float* __restrict__ B,
    float* __restrict__ C, int lda, int ldb, int ldc, int Klen, long csplit)
{
    constexpr int BN   = 64 * NT;
    constexpr int SBW  = BN + 4;           // B smem row stride (floats)
    constexpr int ABUF = 64 * 36;          // floats per A buffer
    constexpr int BUF  = ABUF + 32 * SBW;  // floats per (A+B) buffer
    extern __shared__ float smem[];
    const int tid = threadIdx.x, wid = tid >> 5, lane = tid & 31;
    const int g = lane >> 2, t = lane & 3;
    const int n0 = blockIdx.x * BN;
    const int m0 = blockIdx.y * 64;
    const long kbeg = (long)blockIdx.z * Klen;
    const float* Ab = A + (size_t)m0 * lda + kbeg;
    const float* Bb = B + (size_t)kbeg * ldb + n0;
    const uint32_t sb = smem_u32(smem);
    const int nch = Klen >> 5;
    const int nbw = wid * 8 * NT;          // warp n-base within block

    auto prefetch = [&](int ck, int buf) {
        uint32_t as = sb + buf * BUF * 4;
        uint32_t bs = as + ABUF * 4;
        const float* Ag = Ab + ck * 32;
        #pragma unroll
        for (int q = 0; q < 2; q++) {
            int idx = q * 256 + tid, r = idx >> 3, f = idx & 7;
            cpa16(as + (r * 36 + f * 4) * 4, Ag + (size_t)r * lda + f * 4);
        }
        const float* Bg = Bb + (size_t)ck * 32 * ldb;
        #pragma unroll
        for (int q = 0; q < 2 * NT; q++) {
            int idx = q * 256 + tid, r = idx / (16 * NT), f = idx % (16 * NT);
            cpa16(bs + (r * SBW + f * 4) * 4, Bg + (size_t)r * ldb + f * 4);
        }
        asm volatile("cp.async.commit_group;" ::: "memory");
    };

    float acc[4][NT][4];
    #pragma unroll
    for (int mt = 0; mt < 4; mt++)
        #pragma unroll
        for (int nt = 0; nt < NT; nt++)
            #pragma unroll
            for (int r = 0; r < 4; r++) acc[mt][nt][r] = 0.f;

    prefetch(0, 0);
    for (int it = 0; it < nch; it++) {
        if (it + 1 < nch) {
            prefetch(it + 1, (it + 1) & 1);
            asm volatile("cp.async.wait_group 1;" ::: "memory");
        } else {
            asm volatile("cp.async.wait_group 0;" ::: "memory");
        }
        __syncthreads();
        uint32_t as = sb + (it & 1) * BUF * 4;
        uint32_t bs = as + ABUF * 4;
        #pragma unroll
        for (int ks = 0; ks < 4; ks++) {
            uint32_t a[4][4];
            #pragma unroll
            for (int mt = 0; mt < 4; mt++) {
                uint32_t r0 = as + ((16 * mt + g) * 36 + 8 * ks + t) * 4;
                a[mt][0] = ldsu(r0) + 0x1000u;                 // +0x1000: tf32 round-to-nearest
                a[mt][1] = ldsu(r0 + 8 * 36 * 4) + 0x1000u;
                a[mt][2] = ldsu(r0 + 16) + 0x1000u;
                a[mt][3] = ldsu(r0 + 8 * 36 * 4 + 16) + 0x1000u;
            }
            #pragma unroll
            for (int nt = 0; nt < NT; nt++) {
                uint32_t bo = bs + ((8 * ks + t) * SBW + nbw + 8 * nt + g) * 4;
                uint32_t b0 = ldsu(bo) + 0x1000u;
                uint32_t b1 = ldsu(bo + 4 * SBW * 4) + 0x1000u;
                #pragma unroll
                for (int mt = 0; mt < 4; mt++) hmma(acc[mt][nt], a[mt], b0, b1);
            }
        }
        __syncthreads();
    }

    float* Cb = C + (size_t)blockIdx.z * csplit + (size_t)m0 * ldc + n0 + nbw;
    #pragma unroll
    for (int mt = 0; mt < 4; mt++) {
        #pragma unroll
        for (int nt = 0; nt < NT; nt++) {
            float* p0 = Cb + (size_t)(16 * mt + g) * ldc + 8 * nt + 2 * t;
            p0[0] = acc[mt][nt][0]; p0[1] = acc[mt][nt][1];
            float* p1 = p0 + 8 * (size_t)ldc;
            p1[0] = acc[mt][nt][2]; p1[1] = acc[mt][nt][3];
        }
    }
}

// combine 4 GEMM1 partials + bias, relu -> g_z2
__global__ void k_relu4(const float* __restrict__ b1) {
    int i = blockIdx.x * 256 + threadIdx.x;          // float4 idx < 204800
    const float4* P = (const float4*)g_z2p;
    float4 a = P[i];
    float4 t1 = P[204800 + i], t2 = P[409600 + i], t3 = P[614400 + i];
    a.x += t1.x + t2.x + t3.x; a.y += t1.y + t2.y + t3.y;
    a.z += t1.z + t2.z + t3.z; a.w += t1.w + t2.w + t3.w;
    float4 bb = ((const float4*)b1)[i % 3200];
    float4 o;
    o.x = fmaxf(a.x + bb.x, 0.f); o.y = fmaxf(a.y + bb.y, 0.f);
    o.z = fmaxf(a.z + bb.z, 0.f); o.w = fmaxf(a.w + bb.w, 0.f);
    ((float4*)g_z2)[i] = o;
}

// combine 8 GEMM2 partials + bias, sigmoid -> out
__global__ void k_sig8(const float* __restrict__ b2, float* __restrict__ out) {
    int i = blockIdx.x * 256 + threadIdx.x;          // float4 idx < 102400
    const float4* P = (const float4*)g_yp;
    float4 a = P[i];
    #pragma unroll
    for (int p = 1; p < 8; p++) {
        float4 tv = P[p * 102400 + i];
        a.x += tv.x; a.y += tv.y; a.z += tv.z; a.w += tv.w;
    }
    float4 bb = ((const float4*)b2)[i % 1600];
    a.x = 1.f / (1.f + expf(-(a.x + bb.x)));
    a.y = 1.f / (1.f + expf(-(a.y + bb.y)));
    a.z = 1.f / (1.f + expf(-(a.z + bb.z)));
    a.w = 1.f / (1.f + expf(-(a.w + bb.w)));
    ((float4*)out)[i] = a;
}

// ---------------- launcher ----------------
extern "C" void kernel_launch(void* const* d_in, const int* in_sizes, int n_in,
                              void* d_out, int out_size) {
    (void)in_sizes; (void)n_in; (void)out_size;
    const float* x  = (const float*)d_in[0];
    const int*   ei = (const int*)  d_in[1];
    const float* Wg = (const float*)d_in[2];
    const float* bg = (const float*)d_in[3];
    const float* W1 = (const float*)d_in[4];
    const float* b1 = (const float*)d_in[5];
    const float* W2 = (const float*)d_in[6];
    const float* b2 = (const float*)d_in[7];
    float* out = (float*)d_out;

    float* d_h    = nullptr; cudaGetSymbolAddress((void**)&d_h,    g_h);
    float* d_gram = nullptr; cudaGetSymbolAddress((void**)&d_gram, g_gram);
    float* d_z2p  = nullptr; cudaGetSymbolAddress((void**)&d_z2p,  g_z2p);
    float* d_z2   = nullptr; cudaGetSymbolAddress((void**)&d_z2,   g_z2);
    float* d_yp   = nullptr; cudaGetSymbolAddress((void**)&d_yp,   g_yp);

    // dynamic smem: 2 * (64*36 + 32*(64*NT+4)) floats
    const int smem2 = 2 * (64 * 36 + 32 * 132) * 4;   // NT=2: 52224 B
    const int smem4 = 2 * (64 * 36 + 32 * 260) * 4;   // NT=4: 84992 B
    cudaFuncSetAttribute(k_tgemm<2>, cudaFuncAttributeMaxDynamicSharedMemorySize, smem2);
    cudaFuncSetAttribute(k_tgemm<4>, cudaFuncAttributeMaxDynamicSharedMemorySize, smem4);

    k_zero<<<20, 256>>>();
    k_fill<<<640, 256>>>(ei, ei + NE);
    k_dinv<<<20, 256>>>();
    // h = x @ Wg : M=5120 (80 tiles of 64), N=128, K=256
    k_tgemm<2><<<dim3(1, 80, 1), 256, smem2>>>(x, Wg, d_h, TBLD, LAT, LAT, TBLD, 0);
    k_gather_z<<<640, 256>>>(bg);
    k_gram<<<NG, 256>>>();
    // GEMM1: [64,6400] @ [6400,12800], block-N 256, split-K=4 -> 200 CTAs
    k_tgemm<4><<<dim3(50, 1, 4), 256, smem4>>>(d_gram, W1, d_z2p, N2, H1, H1, 1600,
                                               (long)NG * H1);
    k_relu4<<<800, 256>>>(b1);
    // GEMM2: [64,12800] @ [12800,6400], block-N 256, split-K=8 -> 200 CTAs
    k_tgemm<4><<<dim3(25, 1, 8), 256, smem4>>>(d_z2, W2, d_yp, H1, N2, N2, 1600,
                                               (long)NG * N2);
    k_sig8<<<400, 256>>>(b2, out);
}

// round 5
// speedup vs baseline: 2.6321x; 1.1947x over previous
#include <cuda_runtime.h>
#include <cstdint>

#define NN 5120
#define NE 163840
#define TBLD 256
#define LAT 128
#define NG 64
#define NNEU 80
#define N2 6400
#define H1 12800

#define SK1 6     // GEMM1 split-K
#define SK2 12    // GEMM2 split-K

// ---------------- device scratch ----------------
__device__ int   g_deg[NN];
__device__ int   g_srclist[NN * 128];
__device__ float g_dinv[NN];
__device__ float g_h[NN * LAT];
__device__ float g_z[NN * LAT];
__device__ float g_gram[NG * N2];          // pre-rounded to tf32-nearest
__device__ float g_z2p[(size_t)SK1 * NG * H1];
__device__ float g_z2[NG * H1];            // pre-rounded to tf32-nearest
__device__ float g_yp[(size_t)SK2 * NG * N2];

__device__ __forceinline__ float preround(float v) {
    return __uint_as_float(__float_as_uint(v) + 0x1000u);
}

// ---------------- graph-side kernels ----------------
__global__ void k_zero() {
    int i = blockIdx.x * 256 + threadIdx.x;
    if (i < NN) g_deg[i] = 0;
}

__global__ void k_fill(const int* __restrict__ src, const int* __restrict__ dst) {
    int e = blockIdx.x * 256 + threadIdx.x;
    if (e >= NE) return;
    int d = dst[e];
    int slot = atomicAdd(&g_deg[d], 1);
    if (slot < 128) g_srclist[(d << 7) + slot] = src[e];
}

__global__ void k_dinv() {
    int i = blockIdx.x * 256 + threadIdx.x;
    if (i < NN) {
        int c = g_deg[i];
        g_dinv[i] = (c > 0) ? rsqrtf((float)c) : 0.0f;
    }
}

__global__ void k_gather_z(const float* __restrict__ bg) {
    int w = (blockIdx.x * blockDim.x + threadIdx.x) >> 5;
    int lane = threadIdx.x & 31;
    if (w >= NN) return;
    int cnt = g_deg[w];
    if (cnt > 128) cnt = 128;
    const int* sl = g_srclist + (w << 7);
    float4 acc = make_float4(0.f, 0.f, 0.f, 0.f);
    #pragma unroll 4
    for (int e = 0; e < cnt; e++) {
        int s = sl[e];
        float wt = g_dinv[s];
        const float4 h4 = *(const float4*)&g_h[(s << 7) + (lane << 2)];
        acc.x += wt * h4.x; acc.y += wt * h4.y;
        acc.z += wt * h4.z; acc.w += wt * h4.w;
    }
    float dv = g_dinv[w];
    float4 bb = ((const float4*)bg)[lane];
    float4 z;
    z.x = fmaxf(dv * acc.x + bb.x, 0.f);
    z.y = fmaxf(dv * acc.y + bb.y, 0.f);
    z.z = fmaxf(dv * acc.z + bb.z, 0.f);
    z.w = fmaxf(dv * acc.w + bb.w, 0.f);
    *(float4*)&g_z[(w << 7) + (lane << 2)] = z;
}

__global__ void k_gram() {
    __shared__ float zt[128][81];
    const int b = blockIdx.x;
    const int tid = threadIdx.x;
    #pragma unroll
    for (int i = 0; i < 10; i++) {
        int f = tid + i * 256;
        int row = f >> 5, k4 = f & 31;
        float4 v = *(const float4*)&g_z[((b * NNEU + row) << 7) + (k4 << 2)];
        zt[k4 * 4 + 0][row] = v.x; zt[k4 * 4 + 1][row] = v.y;
        zt[k4 * 4 + 2][row] = v.z; zt[k4 * 4 + 3][row] = v.w;
    }
    __syncthreads();
    const int tx = tid & 15, ty = tid >> 4;
    const int i0 = ty * 5, j0 = tx * 5;
    float acc[5][5];
    #pragma unroll
    for (int i = 0; i < 5; i++)
        #pragma unroll
        for (int j = 0; j < 5; j++) acc[i][j] = 0.f;
    #pragma unroll 4
    for (int k = 0; k < 128; k++) {
        float a[5], c[5];
        #pragma unroll
        for (int u = 0; u < 5; u++) { a[u] = zt[k][i0 + u]; c[u] = zt[k][j0 + u]; }
        #pragma unroll
        for (int i = 0; i < 5; i++)
            #pragma unroll
            for (int j = 0; j < 5; j++) acc[i][j] += a[i] * c[j];
    }
    float* G = g_gram + b * N2;
    #pragma unroll
    for (int i = 0; i < 5; i++)
        #pragma unroll
        for (int j = 0; j < 5; j++)
            G[(i0 + i) * NNEU + j0 + j] = preround(acc[i][j]);  // tf32 pre-round (A of GEMM1)
}

// ---------------- tf32 mma.sync GEMM ----------------
__device__ __forceinline__ uint32_t smem_u32(const void* p) {
    return (uint32_t)__cvta_generic_to_shared(p);
}
__device__ __forceinline__ void cpa16(uint32_t dst, const void* src) {
    asm volatile("cp.async.cg.shared.global [%0], [%1], 16;" :: "r"(dst), "l"(src));
}
__device__ __forceinline__ uint32_t ldsu(uint32_t addr) {
    uint32_t v; asm volatile("ld.shared.b32 %0, [%1];" : "=r"(v) : "r"(addr)); return v;
}
__device__ __forceinline__ void hmma(float* c, const uint32_t* a, uint32_t b0, uint32_t b1) {
    asm volatile(
        "mma.sync.aligned.m16n8k8.row.col.f32.tf32.tf32.f32 "
        "{%0,%1,%2,%3}, {%4,%5,%6,%7}, {%8,%9}, {%0,%1,%2,%3};"
        : "+f"(c[0]), "+f"(c[1]), "+f"(c[2]), "+f"(c[3])
        : "r"(a[0]), "r"(a[1]), "r"(a[2]), "r"(a[3]), "r"(b0), "r"(b1));
}

// Block tile: M=64 x N=64*NT, K-chunk=32, 8 warps (each: 4 m16-tiles x NT n8-tiles).
// RA: round A fragments in-kernel (0 when A was pre-rounded by its producer).
// K range per z-slice: chunks [ctot*z/gz, ctot*(z+1)/gz).
template<int NT, int RA>
__global__ __launch_bounds__(256, 2) void k_tgemm(
    const float* __restrict__ A, const float* __restrict__ B,
    float* __restrict__ C, int lda, int ldb, int ldc, int ctot, long csplit)
{
    constexpr int BN   = 64 * NT;
    constexpr int SBW  = BN + 4;
    constexpr int ABUF = 64 * 36;
    constexpr int BUF  = ABUF + 32 * SBW;
    extern __shared__ float smem[];
    const int tid = threadIdx.x, wid = tid >> 5, lane = tid & 31;
    const int g = lane >> 2, t = lane & 3;
    const int n0 = blockIdx.x * BN;
    const int m0 = blockIdx.y * 64;
    const int c0 = (int)((long)ctot * blockIdx.z / gridDim.z);
    const int c1 = (int)((long)ctot * (blockIdx.z + 1) / gridDim.z);
    const int nch = c1 - c0;
    const float* Ab = A + (size_t)m0 * lda + (size_t)c0 * 32;
    const float* Bb = B + (size_t)c0 * 32 * ldb + n0;
    const uint32_t sb = smem_u32(smem);
    const int nbw = wid * 8 * NT;

    auto prefetch = [&](int ck, int buf) {
        uint32_t as = sb + buf * BUF * 4;
        uint32_t bs = as + ABUF * 4;
        const float* Ag = Ab + ck * 32;
        #pragma unroll
        for (int q = 0; q < 2; q++) {
            int idx = q * 256 + tid, r = idx >> 3, f = idx & 7;
            cpa16(as + (r * 36 + f * 4) * 4, Ag + (size_t)r * lda + f * 4);
        }
        const float* Bg = Bb + (size_t)ck * 32 * ldb;
        #pragma unroll
        for (int q = 0; q < 2 * NT; q++) {
            int idx = q * 256 + tid, r = idx / (16 * NT), f = idx % (16 * NT);
            cpa16(bs + (r * SBW + f * 4) * 4, Bg + (size_t)r * ldb + f * 4);
        }
        asm volatile("cp.async.commit_group;" ::: "memory");
    };

    float acc[4][NT][4];
    #pragma unroll
    for (int mt = 0; mt < 4; mt++)
        #pragma unroll
        for (int nt = 0; nt < NT; nt++)
            #pragma unroll
            for (int r = 0; r < 4; r++) acc[mt][nt][r] = 0.f;

    prefetch(0, 0);
    for (int it = 0; it < nch; it++) {
        if (it + 1 < nch) {
            prefetch(it + 1, (it + 1) & 1);
            asm volatile("cp.async.wait_group 1;" ::: "memory");
        } else {
            asm volatile("cp.async.wait_group 0;" ::: "memory");
        }
        __syncthreads();
        uint32_t as = sb + (it & 1) * BUF * 4;
        uint32_t bs = as + ABUF * 4;
        #pragma unroll
        for (int ks = 0; ks < 4; ks++) {
            uint32_t a[4][4];
            #pragma unroll
            for (int mt = 0; mt < 4; mt++) {
                uint32_t r0 = as + ((16 * mt + g) * 36 + 8 * ks + t) * 4;
                a[mt][0] = ldsu(r0);
                a[mt][1] = ldsu(r0 + 8 * 36 * 4);
                a[mt][2] = ldsu(r0 + 16);
                a[mt][3] = ldsu(r0 + 8 * 36 * 4 + 16);
                if (RA) {
                    a[mt][0] += 0x1000u; a[mt][1] += 0x1000u;
                    a[mt][2] += 0x1000u; a[mt][3] += 0x1000u;
                }
            }
            #pragma unroll
            for (int nt = 0; nt < NT; nt++) {
                uint32_t bo = bs + ((8 * ks + t) * SBW + nbw + 8 * nt + g) * 4;
                uint32_t b0 = ldsu(bo) + 0x1000u;
                uint32_t b1 = ldsu(bo + 4 * SBW * 4) + 0x1000u;
                #pragma unroll
                for (int mt = 0; mt < 4; mt++) hmma(acc[mt][nt], a[mt], b0, b1);
            }
        }
        __syncthreads();
    }

    float* Cb = C + (size_t)blockIdx.z * csplit + (size_t)m0 * ldc + n0 + nbw;
    #pragma unroll
    for (int mt = 0; mt < 4; mt++) {
        #pragma unroll
        for (int nt = 0; nt < NT; nt++) {
            float* p0 = Cb + (size_t)(16 * mt + g) * ldc + 8 * nt + 2 * t;
            p0[0] = acc[mt][nt][0]; p0[1] = acc[mt][nt][1];
            float* p1 = p0 + 8 * (size_t)ldc;
            p1[0] = acc[mt][nt][2]; p1[1] = acc[mt][nt][3];
        }
    }
}

// combine SK1 GEMM1 partials + bias, relu, tf32 pre-round -> g_z2
__global__ void k_relu6(const float* __restrict__ b1) {
    int i = blockIdx.x * 256 + threadIdx.x;          // float4 idx < 204800
    const float4* P = (const float4*)g_z2p;
    float4 a = P[i];
    #pragma unroll
    for (int s = 1; s < SK1; s++) {
        float4 tv = P[(size_t)s * 204800 + i];
        a.x += tv.x; a.y += tv.y; a.z += tv.z; a.w += tv.w;
    }
    float4 bb = ((const float4*)b1)[i % 3200];
    float4 o;
    o.x = preround(fmaxf(a.x + bb.x, 0.f));
    o.y = preround(fmaxf(a.y + bb.y, 0.f));
    o.z = preround(fmaxf(a.z + bb.z, 0.f));
    o.w = preround(fmaxf(a.w + bb.w, 0.f));
    ((float4*)g_z2)[i] = o;
}

// combine SK2 GEMM2 partials + bias, sigmoid -> out
__global__ void k_sig12(const float* __restrict__ b2, float* __restrict__ out) {
    int i = blockIdx.x * 256 + threadIdx.x;          // float4 idx < 102400
    const float4* P = (const float4*)g_yp;
    float4 a = P[i];
    #pragma unroll
    for (int p = 1; p < SK2; p++) {
        float4 tv = P[(size_t)p * 102400 + i];
        a.x += tv.x; a.y += tv.y; a.z += tv.z; a.w += tv.w;
    }
    float4 bb = ((const float4*)b2)[i % 1600];
    a.x = 1.f / (1.f + expf(-(a.x + bb.x)));
    a.y = 1.f / (1.f + expf(-(a.y + bb.y)));
    a.z = 1.f / (1.f + expf(-(a.z + bb.z)));
    a.w = 1.f / (1.f + expf(-(a.w + bb.w)));
    ((float4*)out)[i] = a;
}

// ---------------- launcher ----------------
extern "C" void kernel_launch(void* const* d_in, const int* in_sizes, int n_in,
                              void* d_out, int out_size) {
    (void)in_sizes; (void)n_in; (void)out_size;
    const float* x  = (const float*)d_in[0];
    const int*   ei = (const int*)  d_in[1];
    const float* Wg = (const float*)d_in[2];
    const float* bg = (const float*)d_in[3];
    const float* W1 = (const float*)d_in[4];
    const float* b1 = (const float*)d_in[5];
    const float* W2 = (const float*)d_in[6];
    const float* b2 = (const float*)d_in[7];
    float* out = (float*)d_out;

    float* d_h    = nullptr; cudaGetSymbolAddress((void**)&d_h,    g_h);
    float* d_gram = nullptr; cudaGetSymbolAddress((void**)&d_gram, g_gram);
    float* d_z2p  = nullptr; cudaGetSymbolAddress((void**)&d_z2p,  g_z2p);
    float* d_z2   = nullptr; cudaGetSymbolAddress((void**)&d_z2,   g_z2);
    float* d_yp   = nullptr; cudaGetSymbolAddress((void**)&d_yp,   g_yp);

    // dynamic smem: 2 * (64*36 + 32*(64*NT+4)) floats
    const int smem1 = 2 * (64 * 36 + 32 * 68) * 4;    // NT=1: 35840 B
    const int smem4 = 2 * (64 * 36 + 32 * 260) * 4;   // NT=4: 84992 B
    cudaFuncSetAttribute(k_tgemm<1, 1>, cudaFuncAttributeMaxDynamicSharedMemorySize, smem1);
    cudaFuncSetAttribute(k_tgemm<4, 0>, cudaFuncAttributeMaxDynamicSharedMemorySize, smem4);

    k_zero<<<20, 256>>>();
    k_fill<<<640, 256>>>(ei, ei + NE);
    k_dinv<<<20, 256>>>();
    // h = x @ Wg : M=5120 (80 tiles), N=128 (2 tiles of 64), K=256 (8 chunks)
    k_tgemm<1, 1><<<dim3(2, 80, 1), 256, smem1>>>(x, Wg, d_h, TBLD, LAT, LAT, 8, 0);
    k_gather_z<<<640, 256>>>(bg);
    k_gram<<<NG, 256>>>();
    // GEMM1: [64,6400] @ [6400,12800], 50 N-tiles x splitK 6 = 300 CTAs (200 chunks)
    k_tgemm<4, 0><<<dim3(50, 1, SK1), 256, smem4>>>(d_gram, W1, d_z2p, N2, H1, H1,
                                                    200, (long)NG * H1);
    k_relu6<<<800, 256>>>(b1);
    // GEMM2: [64,12800] @ [12800,6400], 25 N-tiles x splitK 12 = 300 CTAs (400 chunks)
    k_tgemm<4, 0><<<dim3(25, 1, SK2), 256, smem4>>>(d_z2, W2, d_yp, H1, N2, N2,
                                                    400, (long)NG * N2);
    k_sig12<<<400, 256>>>(b2, out);
}

// round 7
// speedup vs baseline: 2.8613x; 1.0871x over previous
#include <cuda_runtime.h>
#include <cstdint>

#define NN 5120
#define NE 163840
#define TBLD 256
#define LAT 128
#define NG 64
#define NNEU 80
#define N2 6400
#define H1 12800

#define SK1 5     // GEMM1 split-K  (50 N-tiles x 5 = 250 CTAs, single wave)
#define SK2 11    // GEMM2 split-K  (25 N-tiles x 11 = 275 CTAs, single wave)

// ---------------- device scratch ----------------
__device__ int   g_deg[NN];
__device__ int   g_srclist[NN * 128];
__device__ float g_dinv[NN];
__device__ float g_h[NN * LAT];
__device__ float g_z[NN * LAT];
__device__ float g_gram[NG * N2];          // pre-rounded to tf32-nearest
__device__ float g_z2p[(size_t)SK1 * NG * H1];
__device__ float g_z2[NG * H1];            // pre-rounded to tf32-nearest
__device__ float g_yp[(size_t)SK2 * NG * N2];

__device__ __forceinline__ float preround(float v) {
    return __uint_as_float(__float_as_uint(v) + 0x1000u);
}

// ---------------- graph-side kernels ----------------
__global__ void k_zero() {
    int i = blockIdx.x * 256 + threadIdx.x;
    if (i < NN) g_deg[i] = 0;
}

__global__ void k_fill(const int* __restrict__ src, const int* __restrict__ dst) {
    int e = blockIdx.x * 256 + threadIdx.x;
    if (e >= NE) return;
    int d = dst[e];
    int slot = atomicAdd(&g_deg[d], 1);
    if (slot < 128) g_srclist[(d << 7) + slot] = src[e];
}

__global__ void k_dinv() {
    int i = blockIdx.x * 256 + threadIdx.x;
    if (i < NN) {
        int c = g_deg[i];
        g_dinv[i] = (c > 0) ? rsqrtf((float)c) : 0.0f;
    }
}

__global__ void k_gather_z(const float* __restrict__ bg) {
    int w = (blockIdx.x * blockDim.x + threadIdx.x) >> 5;
    int lane = threadIdx.x & 31;
    if (w >= NN) return;
    int cnt = g_deg[w];
    if (cnt > 128) cnt = 128;
    const int* sl = g_srclist + (w << 7);
    float4 acc = make_float4(0.f, 0.f, 0.f, 0.f);
    #pragma unroll 4
    for (int e = 0; e < cnt; e++) {
        int s = sl[e];
        float wt = g_dinv[s];
        const float4 h4 = *(const float4*)&g_h[(s << 7) + (lane << 2)];
        acc.x += wt * h4.x; acc.y += wt * h4.y;
        acc.z += wt * h4.z; acc.w += wt * h4.w;
    }
    float dv = g_dinv[w];
    float4 bb = ((const float4*)bg)[lane];
    float4 z;
    z.x = fmaxf(dv * acc.x + bb.x, 0.f);
    z.y = fmaxf(dv * acc.y + bb.y, 0.f);
    z.z = fmaxf(dv * acc.z + bb.z, 0.f);
    z.w = fmaxf(dv * acc.w + bb.w, 0.f);
    *(float4*)&g_z[(w << 7) + (lane << 2)] = z;
}

__global__ void k_gram() {
    __shared__ float zt[128][81];
    const int b = blockIdx.x;
    const int tid = threadIdx.x;
    #pragma unroll
    for (int i = 0; i < 10; i++) {
        int f = tid + i * 256;
        int row = f >> 5, k4 = f & 31;
        float4 v = *(const float4*)&g_z[((b * NNEU + row) << 7) + (k4 << 2)];
        zt[k4 * 4 + 0][row] = v.x; zt[k4 * 4 + 1][row] = v.y;
        zt[k4 * 4 + 2][row] = v.z; zt[k4 * 4 + 3][row] = v.w;
    }
    __syncthreads();
    const int tx = tid & 15, ty = tid >> 4;
    const int i0 = ty * 5, j0 = tx * 5;
    float acc[5][5];
    #pragma unroll
    for (int i = 0; i < 5; i++)
        #pragma unroll
        for (int j = 0; j < 5; j++) acc[i][j] = 0.f;
    #pragma unroll 4
    for (int k = 0; k < 128; k++) {
        float a[5], c[5];
        #pragma unroll
        for (int u = 0; u < 5; u++) { a[u] = zt[k][i0 + u]; c[u] = zt[k][j0 + u]; }
        #pragma unroll
        for (int i = 0; i < 5; i++)
            #pragma unroll
            for (int j = 0; j < 5; j++) acc[i][j] += a[i] * c[j];
    }
    float* G = g_gram + b * N2;
    #pragma unroll
    for (int i = 0; i < 5; i++)
        #pragma unroll
        for (int j = 0; j < 5; j++)
            G[(i0 + i) * NNEU + j0 + j] = preround(acc[i][j]);
}

// ---------------- tf32 mma.sync helpers ----------------
__device__ __forceinline__ uint32_t smem_u32(const void* p) {
    return (uint32_t)__cvta_generic_to_shared(p);
}
__device__ __forceinline__ void cpa16(uint32_t dst, const void* src) {
    asm volatile("cp.async.cg.shared.global [%0], [%1], 16;" :: "r"(dst), "l"(src));
}
__device__ __forceinline__ uint32_t ldsu(uint32_t addr) {
    uint32_t v; asm volatile("ld.shared.b32 %0, [%1];" : "=r"(v) : "r"(addr)); return v;
}
__device__ __forceinline__ void hmma(float* c, const uint32_t* a, uint32_t b0, uint32_t b1) {
    asm volatile(
        "mma.sync.aligned.m16n8k8.row.col.f32.tf32.tf32.f32 "
        "{%0,%1,%2,%3}, {%4,%5,%6,%7}, {%8,%9}, {%0,%1,%2,%3};"
        : "+f"(c[0]), "+f"(c[1]), "+f"(c[2]), "+f"(c[3])
        : "r"(a[0]), "r"(a[1]), "r"(a[2]), "r"(a[3]), "r"(b0), "r"(b1));
}

// ============ big-GEMM kernel: 128 threads / 4 warps, M=64 x N=256 ============
// Each warp: 4 m16-tiles x 8 n8-tiles (64 N-cols). A smem 64x36, B smem 32x264
// (both layouts bank-conflict-free: A bank=4g+t, B bank=8t+g).
// A is pre-rounded by its producer; B gets +0x1000 in-kernel.
#define SBW4 264
#define ABUF4 (64 * 36)
#define BUF4 (ABUF4 + 32 * SBW4)

__global__ __launch_bounds__(128, 2) void k_tgemm4(
    const float* __restrict__ A, const float* __restrict__ B,
    float* __restrict__ C, int lda, int ldb, int ldc, int ctot, long csplit)
{
    extern __shared__ float smem[];
    const int tid = threadIdx.x, wid = tid >> 5, lane = tid & 31;
    const int g = lane >> 2, t = lane & 3;
    const int n0 = blockIdx.x * 256;
    const int c0 = (int)((long)ctot * blockIdx.z / gridDim.z);
    const int c1 = (int)((long)ctot * (blockIdx.z + 1) / gridDim.z);
    const int nch = c1 - c0;
    const float* Ab = A + (size_t)c0 * 32;
    const float* Bb = B + (size_t)c0 * 32 * ldb + n0;
    const uint32_t sb = smem_u32(smem);
    const int nb = wid * 64;                 // warp n-base

    auto prefetch = [&](int ck, int buf) {
        uint32_t as = sb + buf * BUF4 * 4;
        uint32_t bs = as + ABUF4 * 4;
        const float* Ag = Ab + ck * 32;
        #pragma unroll
        for (int q = 0; q < 4; q++) {
            int idx = q * 128 + tid, r = idx >> 3, f = idx & 7;
            cpa16(as + (r * 36 + f * 4) * 4, Ag + (size_t)r * lda + f * 4);
        }
        const float* Bg = Bb + (size_t)ck * 32 * ldb;
        #pragma unroll
        for (int q = 0; q < 16; q++) {
            int idx = q * 128 + tid, r = idx >> 6, f = idx & 63;
            cpa16(bs + (r * SBW4 + f * 4) * 4, Bg + (size_t)r * ldb + f * 4);
        }
        asm volatile("cp.async.commit_group;" ::: "memory");
    };

    float acc[4][8][4];
    #pragma unroll
    for (int mt = 0; mt < 4; mt++)
        #pragma unroll
        for (int nt = 0; nt < 8; nt++)
            #pragma unroll
            for (int r = 0; r < 4; r++) acc[mt][nt][r] = 0.f;

    prefetch(0, 0);
    for (int it = 0; it < nch; it++) {
        if (it + 1 < nch) {
            prefetch(it + 1, (it + 1) & 1);
            asm volatile("cp.async.wait_group 1;" ::: "memory");
        } else {
            asm volatile("cp.async.wait_group 0;" ::: "memory");
        }
        __syncthreads();
        uint32_t as = sb + (it & 1) * BUF4 * 4;
        uint32_t bs = as + ABUF4 * 4;
        #pragma unroll
        for (int ks = 0; ks < 4; ks++) {
            uint32_t a[4][4];
            #pragma unroll
            for (int mt = 0; mt < 4; mt++) {
                uint32_t r0 = as + ((16 * mt + g) * 36 + 8 * ks + t) * 4;
                a[mt][0] = ldsu(r0);
                a[mt][1] = ldsu(r0 + 8 * 36 * 4);
                a[mt][2] = ldsu(r0 + 16);
                a[mt][3] = ldsu(r0 + 8 * 36 * 4 + 16);
            }
            #pragma unroll
            for (int nt = 0; nt < 8; nt++) {
                uint32_t bo = bs + ((8 * ks + t) * SBW4 + nb + 8 * nt + g) * 4;
                uint32_t b0 = ldsu(bo) + 0x1000u;
                uint32_t b1 = ldsu(bo + 4 * SBW4 * 4) + 0x1000u;
                #pragma unroll
                for (int mt = 0; mt < 4; mt++) hmma(acc[mt][nt], a[mt], b0, b1);
            }
        }
        __syncthreads();
    }

    float* Cb = C + (size_t)blockIdx.z * csplit + n0 + nb;
    #pragma unroll
    for (int mt = 0; mt < 4; mt++) {
        #pragma unroll
        for (int nt = 0; nt < 8; nt++) {
            float* p0 = Cb + (size_t)(16 * mt + g) * ldc + 8 * nt + 2 * t;
            p0[0] = acc[mt][nt][0]; p0[1] = acc[mt][nt][1];
            float* p1 = p0 + 8 * (size_t)ldc;
            p1[0] = acc[mt][nt][2]; p1[1] = acc[mt][nt][3];
        }
    }
}

// ============ 8-warp template (h-GEMM only), proven in R3/R5 ============
template<int NT, int RA>
__global__ __launch_bounds__(256, 2) void k_tgemm(
    const float* __restrict__ A, const float* __restrict__ B,
    float* __restrict__ C, int lda, int ldb, int ldc, int ctot, long csplit)
{
    constexpr int BN   = 64 * NT;
    constexpr int SBW  = BN + 8;           // pad 8: bank = 8t+g, conflict-free
    constexpr int ABUF = 64 * 36;
    constexpr int BUF  = ABUF + 32 * SBW;
    extern __shared__ float smem[];
    const int tid = threadIdx.x, wid = tid >> 5, lane = tid & 31;
    const int g = lane >> 2, t = lane & 3;
    const int n0 = blockIdx.x * BN;
    const int m0 = blockIdx.y * 64;
    const int c0 = (int)((long)ctot * blockIdx.z / gridDim.z);
    const int c1 = (int)((long)ctot * (blockIdx.z + 1) / gridDim.z);
    const int nch = c1 - c0;
    const float* Ab = A + (size_t)m0 * lda + (size_t)c0 * 32;
    const float* Bb = B + (size_t)c0 * 32 * ldb + n0;
    const uint32_t sb = smem_u32(smem);
    const int nbw = wid * 8 * NT;

    auto prefetch = [&](int ck, int buf) {
        uint32_t as = sb + buf * BUF * 4;
        uint32_t bs = as + ABUF * 4;
        const float* Ag = Ab + ck * 32;
        #pragma unroll
        for (int q = 0; q < 2; q++) {
            int idx = q * 256 + tid, r = idx >> 3, f = idx & 7;
            cpa16(as + (r * 36 + f * 4) * 4, Ag + (size_t)r * lda + f * 4);
        }
        const float* Bg = Bb + (size_t)ck * 32 * ldb;
        #pragma unroll
        for (int q = 0; q < 2 * NT; q++) {
            int idx = q * 256 + tid, r = idx / (16 * NT), f = idx % (16 * NT);
            cpa16(bs + (r * SBW + f * 4) * 4, Bg + (size_t)r * ldb + f * 4);
        }
        asm volatile("cp.async.commit_group;" ::: "memory");
    };

    float acc[4][NT][4];
    #pragma unroll
    for (int mt = 0; mt < 4; mt++)
        #pragma unroll
        for (int nt = 0; nt < NT; nt++)
            #pragma unroll
            for (int r = 0; r < 4; r++) acc[mt][nt][r] = 0.f;

    prefetch(0, 0);
    for (int it = 0; it < nch; it++) {
        if (it + 1 < nch) {
            prefetch(it + 1, (it + 1) & 1);
            asm volatile("cp.async.wait_group 1;" ::: "memory");
        } else {
            asm volatile("cp.async.wait_group 0;" ::: "memory");
        }
        __syncthreads();
        uint32_t as = sb + (it & 1) * BUF * 4;
        uint32_t bs = as + ABUF * 4;
        #pragma unroll
        for (int ks = 0; ks < 4; ks++) {
            uint32_t a[4][4];
            #pragma unroll
            for (int mt = 0; mt < 4; mt++) {
                uint32_t r0 = as + ((16 * mt + g) * 36 + 8 * ks + t) * 4;
                a[mt][0] = ldsu(r0);
                a[mt][1] = ldsu(r0 + 8 * 36 * 4);
                a[mt][2] = ldsu(r0 + 16);
                a[mt][3] = ldsu(r0 + 8 * 36 * 4 + 16);
                if (RA) {
                    a[mt][0] += 0x1000u; a[mt][1] += 0x1000u;
                    a[mt][2] += 0x1000u; a[mt][3] += 0x1000u;
                }
            }
            #pragma unroll
            for (int nt = 0; nt < NT; nt++) {
                uint32_t bo = bs + ((8 * ks + t) * SBW + nbw + 8 * nt + g) * 4;
                uint32_t b0 = ldsu(bo) + 0x1000u;
                uint32_t b1 = ldsu(bo + 4 * SBW * 4) + 0x1000u;
                #pragma unroll
                for (int mt = 0; mt < 4; mt++) hmma(acc[mt][nt], a[mt], b0, b1);
            }
        }
        __syncthreads();
    }

    float* Cb = C + (size_t)blockIdx.z * csplit + (size_t)m0 * ldc + n0 + nbw;
    #pragma unroll
    for (int mt = 0; mt < 4; mt++) {
        #pragma unroll
        for (int nt = 0; nt < NT; nt++) {
            float* p0 = Cb + (size_t)(16 * mt + g) * ldc + 8 * nt + 2 * t;
            p0[0] = acc[mt][nt][0]; p0[1] = acc[mt][nt][1];
            float* p1 = p0 + 8 * (size_t)ldc;
            p1[0] = acc[mt][nt][2]; p1[1] = acc[mt][nt][3];
        }
    }
}

// combine SK1 GEMM1 partials + bias, relu, tf32 pre-round -> g_z2
__global__ void k_relu_c(const float* __restrict__ b1) {
    int i = blockIdx.x * 256 + threadIdx.x;          // float4 idx < 204800
    const float4* P = (const float4*)g_z2p;
    float4 a = P[i];
    #pragma unroll
    for (int s = 1; s < SK1; s++) {
        float4 tv = P[(size_t)s * 204800 + i];
        a.x += tv.x; a.y += tv.y; a.z += tv.z; a.w += tv.w;
    }
    float4 bb = ((const float4*)b1)[i % 3200];
    float4 o;
    o.x = preround(fmaxf(a.x + bb.x, 0.f));
    o.y = preround(fmaxf(a.y + bb.y, 0.f));
    o.z = preround(fmaxf(a.z + bb.z, 0.f));
    o.w = preround(fmaxf(a.w + bb.w, 0.f));
    ((float4*)g_z2)[i] = o;
}

// combine SK2 GEMM2 partials + bias, sigmoid -> out
__global__ void k_sig_c(const float* __restrict__ b2, float* __restrict__ out) {
    int i = blockIdx.x * 256 + threadIdx.x;          // float4 idx < 102400
    const float4* P = (const float4*)g_yp;
    float4 a = P[i];
    #pragma unroll
    for (int p = 1; p < SK2; p++) {
        float4 tv = P[(size_t)p * 102400 + i];
        a.x += tv.x; a.y += tv.y; a.z += tv.z; a.w += tv.w;
    }
    float4 bb = ((const float4*)b2)[i % 1600];
    a.x = 1.f / (1.f + expf(-(a.x + bb.x)));
    a.y = 1.f / (1.f + expf(-(a.y + bb.y)));
    a.z = 1.f / (1.f + expf(-(a.z + bb.z)));
    a.w = 1.f / (1.f + expf(-(a.w + bb.w)));
    ((float4*)out)[i] = a;
}

// ---------------- launcher ----------------
extern "C" void kernel_launch(void* const* d_in, const int* in_sizes, int n_in,
                              void* d_out, int out_size) {
    (void)in_sizes; (void)n_in; (void)out_size;
    const float* x  = (const float*)d_in[0];
    const int*   ei = (const int*)  d_in[1];
    const float* Wg = (const float*)d_in[2];
    const float* bg = (const float*)d_in[3];
    const float* W1 = (const float*)d_in[4];
    const float* b1 = (const float*)d_in[5];
    const float* W2 = (const float*)d_in[6];
    const float* b2 = (const float*)d_in[7];
    float* out = (float*)d_out;

    float* d_h    = nullptr; cudaGetSymbolAddress((void**)&d_h,    g_h);
    float* d_gram = nullptr; cudaGetSymbolAddress((void**)&d_gram, g_gram);
    float* d_z2p  = nullptr; cudaGetSymbolAddress((void**)&d_z2p,  g_z2p);
    float* d_z2   = nullptr; cudaGetSymbolAddress((void**)&d_z2,   g_z2);
    float* d_yp   = nullptr; cudaGetSymbolAddress((void**)&d_yp,   g_yp);

    const int smem2 = 2 * (64 * 36 + 32 * 136) * 4;   // NT=2 (h-GEMM): 53248 B
    const int smem4 = 2 * BUF4 * 4;                   // 4-warp kernel: 86016 B
    cudaFuncSetAttribute(k_tgemm<2, 1>, cudaFuncAttributeMaxDynamicSharedMemorySize, smem2);
    cudaFuncSetAttribute(k_tgemm4, cudaFuncAttributeMaxDynamicSharedMemorySize, smem4);

    k_zero<<<20, 256>>>();
    k_fill<<<640, 256>>>(ei, ei + NE);
    k_dinv<<<20, 256>>>();
    // h = x @ Wg : M=5120 (80 tiles), N=128 (NT=2), K=256 (8 chunks)
    k_tgemm<2, 1><<<dim3(1, 80, 1), 256, smem2>>>(x, Wg, d_h, TBLD, LAT, LAT, 8, 0);
    k_gather_z<<<640, 256>>>(bg);
    k_gram<<<NG, 256>>>();
    // GEMM1: [64,6400] @ [6400,12800], 50 N-tiles x splitK 5 = 250 CTAs (200 chunks)
    k_tgemm4<<<dim3(50, 1, SK1), 128, smem4>>>(d_gram, W1, d_z2p, N2, H1, H1,
                                               200, (long)NG * H1);
    k_relu_c<<<800, 256>>>(b1);
    // GEMM2: [64,12800] @ [12800,6400], 25 N-tiles x splitK 11 = 275 CTAs (400 chunks)
    k_tgemm4<<<dim3(25, 1, SK2), 128, smem4>>>(d_z2, W2, d_yp, H1, N2, N2,
                                               400, (long)NG * N2);
    k_sig_c<<<400, 256>>>(b2, out);
}

// round 10
// speedup vs baseline: 2.9243x; 1.0220x over previous
#include <cuda_runtime.h>
#include <cstdint>

#define NN 5120
#define NE 163840
#define TBLD 256
#define LAT 128
#define NG 64
#define NNEU 80
#define N2 6400
#define H1 12800

#define SK1 3     // GEMM1 split-K  (100 N-tiles x 3 = 300 CTAs)
#define SK2 6     // GEMM2 split-K  (50 N-tiles x 6 = 300 CTAs)

// ---------------- device scratch ----------------
__device__ int   g_deg[NN];
__device__ int   g_srclist[NN * 128];
__device__ float g_dinv[NN];
__device__ float g_h[NN * LAT];
__device__ float g_z[NN * LAT];
__device__ float g_gram[NG * N2];          // pre-rounded to tf32-nearest
__device__ float g_z2p[(size_t)SK1 * NG * H1];
__device__ float g_z2[NG * H1];            // pre-rounded to tf32-nearest
__device__ float g_yp[(size_t)SK2 * NG * N2];

__device__ __forceinline__ float preround(float v) {
    return __uint_as_float(__float_as_uint(v) + 0x1000u);
}

// ---------------- graph-side kernels ----------------
__global__ void k_zero() {
    int i = blockIdx.x * 256 + threadIdx.x;
    if (i < NN) g_deg[i] = 0;
}

__global__ void k_fill(const int* __restrict__ src, const int* __restrict__ dst) {
    int e = blockIdx.x * 256 + threadIdx.x;
    if (e >= NE) return;
    int d = dst[e];
    int slot = atomicAdd(&g_deg[d], 1);
    if (slot < 128) g_srclist[(d << 7) + slot] = src[e];
}

__global__ void k_dinv() {
    int i = blockIdx.x * 256 + threadIdx.x;
    if (i < NN) {
        int c = g_deg[i];
        g_dinv[i] = (c > 0) ? rsqrtf((float)c) : 0.0f;
    }
}

__global__ void k_gather_z(const float* __restrict__ bg) {
    int w = (blockIdx.x * blockDim.x + threadIdx.x) >> 5;
    int lane = threadIdx.x & 31;
    if (w >= NN) return;
    int cnt = g_deg[w];
    if (cnt > 128) cnt = 128;
    const int* sl = g_srclist + (w << 7);
    float4 acc = make_float4(0.f, 0.f, 0.f, 0.f);
    #pragma unroll 4
    for (int e = 0; e < cnt; e++) {
        int s = sl[e];
        float wt = g_dinv[s];
        const float4 h4 = *(const float4*)&g_h[(s << 7) + (lane << 2)];
        acc.x += wt * h4.x; acc.y += wt * h4.y;
        acc.z += wt * h4.z; acc.w += wt * h4.w;
    }
    float dv = g_dinv[w];
    float4 bb = ((const float4*)bg)[lane];
    float4 z;
    z.x = fmaxf(dv * acc.x + bb.x, 0.f);
    z.y = fmaxf(dv * acc.y + bb.y, 0.f);
    z.z = fmaxf(dv * acc.z + bb.z, 0.f);
    z.w = fmaxf(dv * acc.w + bb.w, 0.f);
    *(float4*)&g_z[(w << 7) + (lane << 2)] = z;
}

__global__ void k_gram() {
    __shared__ float zt[128][81];
    const int b = blockIdx.x;
    const int tid = threadIdx.x;
    #pragma unroll
    for (int i = 0; i < 10; i++) {
        int f = tid + i * 256;
        int row = f >> 5, k4 = f & 31;
        float4 v = *(const float4*)&g_z[((b * NNEU + row) << 7) + (k4 << 2)];
        zt[k4 * 4 + 0][row] = v.x; zt[k4 * 4 + 1][row] = v.y;
        zt[k4 * 4 + 2][row] = v.z; zt[k4 * 4 + 3][row] = v.w;
    }
    __syncthreads();
    const int tx = tid & 15, ty = tid >> 4;
    const int i0 = ty * 5, j0 = tx * 5;
    float acc[5][5];
    #pragma unroll
    for (int i = 0; i < 5; i++)
        #pragma unroll
        for (int j = 0; j < 5; j++) acc[i][j] = 0.f;
    #pragma unroll 4
    for (int k = 0; k < 128; k++) {
        float a[5], c[5];
        #pragma unroll
        for (int u = 0; u < 5; u++) { a[u] = zt[k][i0 + u]; c[u] = zt[k][j0 + u]; }
        #pragma unroll
        for (int i = 0; i < 5; i++)
            #pragma unroll
            for (int j = 0; j < 5; j++) acc[i][j] += a[i] * c[j];
    }
    float* G = g_gram + b * N2;
    #pragma unroll
    for (int i = 0; i < 5; i++)
        #pragma unroll
        for (int j = 0; j < 5; j++)
            G[(i0 + i) * NNEU + j0 + j] = preround(acc[i][j]);
}

// ---------------- tf32 mma.sync helpers ----------------
__device__ __forceinline__ uint32_t smem_u32(const void* p) {
    return (uint32_t)__cvta_generic_to_shared(p);
}
__device__ __forceinline__ void cpa16(uint32_t dst, const void* src) {
    asm volatile("cp.async.cg.shared.global [%0], [%1], 16;" :: "r"(dst), "l"(src));
}
__device__ __forceinline__ uint32_t ldsu(uint32_t addr) {
    uint32_t v; asm volatile("ld.shared.b32 %0, [%1];" : "=r"(v) : "r"(addr)); return v;
}
__device__ __forceinline__ void hmma(float* c, const uint32_t* a, uint32_t b0, uint32_t b1) {
    asm volatile(
        "mma.sync.aligned.m16n8k8.row.col.f32.tf32.tf32.f32 "
        "{%0,%1,%2,%3}, {%4,%5,%6,%7}, {%8,%9}, {%0,%1,%2,%3};"
        : "+f"(c[0]), "+f"(c[1]), "+f"(c[2]), "+f"(c[3])
        : "r"(a[0]), "r"(a[1]), "r"(a[2]), "r"(a[3]), "r"(b0), "r"(b1));
}

// ============ big-GEMM: 4-stage cp.async pipeline (tail-safe waits) ============
// 128 threads / 4 warps, tile M=64 x N=128; warp = 4 m16-tiles x 4 n8-tiles.
// Stage: A 64x36 floats + B 32x136 floats = 26624 B; 4 stages = 106496 B.
// Banks: A frag 4g+t (distinct), B frag 8t+g (distinct) -> conflict-free.
// A pre-rounded by producer; B +0x1000 in-kernel. A is L2-resident.
#define SSBW 136
#define SABUF (64 * 36)
#define SSTAGE (SABUF + 32 * SSBW)          // floats per stage

__global__ __launch_bounds__(128, 2) void k_tgemm4s(
    const float* __restrict__ A, const float* __restrict__ B,
    float* __restrict__ C, int lda, int ldb, int ldc, int ctot, long csplit)
{
    extern __shared__ float smem[];
    const int tid = threadIdx.x, wid = tid >> 5, lane = tid & 31;
    const int g = lane >> 2, t = lane & 3;
    const int n0 = blockIdx.x * 128;
    const int c0 = (int)((long)ctot * blockIdx.z / gridDim.z);
    const int c1 = (int)((long)ctot * (blockIdx.z + 1) / gridDim.z);
    const int nch = c1 - c0;
    const float* Ab = A + (size_t)c0 * 32;
    const float* Bb = B + (size_t)c0 * 32 * ldb + n0;
    const uint32_t sb = smem_u32(smem);
    const int nb = wid * 32;                 // warp n-base

    auto prefetch = [&](int ck) {
        uint32_t as = sb + (ck & 3) * SSTAGE * 4;
        uint32_t bs = as + SABUF * 4;
        const float* Ag = Ab + ck * 32;
        #pragma unroll
        for (int q = 0; q < 4; q++) {
            int idx = q * 128 + tid, r = idx >> 3, f = idx & 7;
            cpa16(as + (r * 36 + f * 4) * 4, Ag + (size_t)r * lda + f * 4);
        }
        const float* Bg = Bb + (size_t)ck * 32 * ldb;
        #pragma unroll
        for (int q = 0; q < 8; q++) {
            int idx = q * 128 + tid, r = idx >> 5, f = idx & 31;
            cpa16(bs + (r * SSBW + f * 4) * 4, Bg + (size_t)r * ldb + f * 4);
        }
        asm volatile("cp.async.commit_group;" ::: "memory");
    };

    float acc[4][4][4];
    #pragma unroll
    for (int mt = 0; mt < 4; mt++)
        #pragma unroll
        for (int nt = 0; nt < 4; nt++)
            #pragma unroll
            for (int r = 0; r < 4; r++) acc[mt][nt][r] = 0.f;

    prefetch(0); prefetch(1); prefetch(2);   // nch >= 3 always (>= 66)

    for (int it = 0; it < nch; it++) {
        // Committed groups so far = min(it+3, nch). Guarantee group `it` done:
        // allowed pending = min(it+3, nch) - (it+1).
        if (it + 3 <= nch) {
            asm volatile("cp.async.wait_group 2;" ::: "memory");
        } else if (it + 2 == nch) {
            asm volatile("cp.async.wait_group 1;" ::: "memory");
        } else {
            asm volatile("cp.async.wait_group 0;" ::: "memory");
        }
        __syncthreads();
        uint32_t as = sb + (it & 3) * SSTAGE * 4;
        uint32_t bs = as + SABUF * 4;
        #pragma unroll
        for (int ks = 0; ks < 4; ks++) {
            uint32_t a[4][4];
            #pragma unroll
            for (int mt = 0; mt < 4; mt++) {
                uint32_t r0 = as + ((16 * mt + g) * 36 + 8 * ks + t) * 4;
                a[mt][0] = ldsu(r0);
                a[mt][1] = ldsu(r0 + 8 * 36 * 4);
                a[mt][2] = ldsu(r0 + 16);
                a[mt][3] = ldsu(r0 + 8 * 36 * 4 + 16);
            }
            #pragma unroll
            for (int nt = 0; nt < 4; nt++) {
                uint32_t bo = bs + ((8 * ks + t) * SSBW + nb + 8 * nt + g) * 4;
                uint32_t b0 = ldsu(bo) + 0x1000u;
                uint32_t b1 = ldsu(bo + 4 * SSBW * 4) + 0x1000u;
                #pragma unroll
                for (int mt = 0; mt < 4; mt++) hmma(acc[mt][nt], a[mt], b0, b1);
            }
        }
        __syncthreads();                     // all warps done with stage `it`
        if (it + 3 < nch) prefetch(it + 3);  // reuses stage (it-1)&3: safe
    }

    float* Cb = C + (size_t)blockIdx.z * csplit + n0 + nb;
    #pragma unroll
    for (int mt = 0; mt < 4; mt++) {
        #pragma unroll
        for (int nt = 0; nt < 4; nt++) {
            float* p0 = Cb + (size_t)(16 * mt + g) * ldc + 8 * nt + 2 * t;
            p0[0] = acc[mt][nt][0]; p0[1] = acc[mt][nt][1];
            float* p1 = p0 + 8 * (size_t)ldc;
            p1[0] = acc[mt][nt][2]; p1[1] = acc[mt][nt][3];
        }
    }
}

// ============ 8-warp template (h-GEMM only), proven ============
template<int NT, int RA>
__global__ __launch_bounds__(256, 2) void k_tgemm(
    const float* __restrict__ A, const float* __restrict__ B,
    float* __restrict__ C, int lda, int ldb, int ldc, int ctot, long csplit)
{
    constexpr int BN   = 64 * NT;
    constexpr int SBW  = BN + 8;
    constexpr int ABUF = 64 * 36;
    constexpr int BUF  = ABUF + 32 * SBW;
    extern __shared__ float smem[];
    const int tid = threadIdx.x, wid = tid >> 5, lane = tid & 31;
    const int g = lane >> 2, t = lane & 3;
    const int n0 = blockIdx.x * BN;
    const int m0 = blockIdx.y * 64;
    const int c0 = (int)((long)ctot * blockIdx.z / gridDim.z);
    const int c1 = (int)((long)ctot * (blockIdx.z + 1) / gridDim.z);
    const int nch = c1 - c0;
    const float* Ab = A + (size_t)m0 * lda + (size_t)c0 * 32;
    const float* Bb = B + (size_t)c0 * 32 * ldb + n0;
    const uint32_t sb = smem_u32(smem);
    const int nbw = wid * 8 * NT;

    auto prefetch = [&](int ck, int buf) {
        uint32_t as = sb + buf * BUF * 4;
        uint32_t bs = as + ABUF * 4;
        const float* Ag = Ab + ck * 32;
        #pragma unroll
        for (int q = 0; q < 2; q++) {
            int idx = q * 256 + tid, r = idx >> 3, f = idx & 7;
            cpa16(as + (r * 36 + f * 4) * 4, Ag + (size_t)r * lda + f * 4);
        }
        const float* Bg = Bb + (size_t)ck * 32 * ldb;
        #pragma unroll
        for (int q = 0; q < 2 * NT; q++) {
            int idx = q * 256 + tid, r = idx / (16 * NT), f = idx % (16 * NT);
            cpa16(bs + (r * SBW + f * 4) * 4, Bg + (size_t)r * ldb + f * 4);
        }
        asm volatile("cp.async.commit_group;" ::: "memory");
    };

    float acc[4][NT][4];
    #pragma unroll
    for (int mt = 0; mt < 4; mt++)
        #pragma unroll
        for (int nt = 0; nt < NT; nt++)
            #pragma unroll
            for (int r = 0; r < 4; r++) acc[mt][nt][r] = 0.f;

    prefetch(0, 0);
    for (int it = 0; it < nch; it++) {
        if (it + 1 < nch) {
            prefetch(it + 1, (it + 1) & 1);
            asm volatile("cp.async.wait_group 1;" ::: "memory");
        } else {
            asm volatile("cp.async.wait_group 0;" ::: "memory");
        }
        __syncthreads();
        uint32_t as = sb + (it & 1) * BUF * 4;
        uint32_t bs = as + ABUF * 4;
        #pragma unroll
        for (int ks = 0; ks < 4; ks++) {
            uint32_t a[4][4];
            #pragma unroll
            for (int mt = 0; mt < 4; mt++) {
                uint32_t r0 = as + ((16 * mt + g) * 36 + 8 * ks + t) * 4;
                a[mt][0] = ldsu(r0);
                a[mt][1] = ldsu(r0 + 8 * 36 * 4);
                a[mt][2] = ldsu(r0 + 16);
                a[mt][3] = ldsu(r0 + 8 * 36 * 4 + 16);
                if (RA) {
                    a[mt][0] += 0x1000u; a[mt][1] += 0x1000u;
                    a[mt][2] += 0x1000u; a[mt][3] += 0x1000u;
                }
            }
            #pragma unroll
            for (int nt = 0; nt < NT; nt++) {
                uint32_t bo = bs + ((8 * ks + t) * SBW + nbw + 8 * nt + g) * 4;
                uint32_t b0 = ldsu(bo) + 0x1000u;
                uint32_t b1 = ldsu(bo + 4 * SBW * 4) + 0x1000u;
                #pragma unroll
                for (int mt = 0; mt < 4; mt++) hmma(acc[mt][nt], a[mt], b0, b1);
            }
        }
        __syncthreads();
    }

    float* Cb = C + (size_t)blockIdx.z * csplit + (size_t)m0 * ldc + n0 + nbw;
    #pragma unroll
    for (int mt = 0; mt < 4; mt++) {
        #pragma unroll
        for (int nt = 0; nt < NT; nt++) {
            float* p0 = Cb + (size_t)(16 * mt + g) * ldc + 8 * nt + 2 * t;
            p0[0] = acc[mt][nt][0]; p0[1] = acc[mt][nt][1];
            float* p1 = p0 + 8 * (size_t)ldc;
            p1[0] = acc[mt][nt][2]; p1[1] = acc[mt][nt][3];
        }
    }
}

// combine SK1 GEMM1 partials + bias, relu, tf32 pre-round -> g_z2
__global__ void k_relu_c(const float* __restrict__ b1) {
    int i = blockIdx.x * 256 + threadIdx.x;          // float4 idx < 204800
    const float4* P = (const float4*)g_z2p;
    float4 a = P[i];
    #pragma unroll
    for (int s = 1; s < SK1; s++) {
        float4 tv = P[(size_t)s * 204800 + i];
        a.x += tv.x; a.y += tv.y; a.z += tv.z; a.w += tv.w;
    }
    float4 bb = ((const float4*)b1)[i % 3200];
    float4 o;
    o.x = preround(fmaxf(a.x + bb.x, 0.f));
    o.y = preround(fmaxf(a.y + bb.y, 0.f));
    o.z = preround(fmaxf(a.z + bb.z, 0.f));
    o.w = preround(fmaxf(a.w + bb.w, 0.f));
    ((float4*)g_z2)[i] = o;
}

// combine SK2 GEMM2 partials + bias, sigmoid -> out
__global__ void k_sig_c(const float* __restrict__ b2, float* __restrict__ out) {
    int i = blockIdx.x * 256 + threadIdx.x;          // float4 idx < 102400
    const float4* P = (const float4*)g_yp;
    float4 a = P[i];
    #pragma unroll
    for (int p = 1; p < SK2; p++) {
        float4 tv = P[(size_t)p * 102400 + i];
        a.x += tv.x; a.y += tv.y; a.z += tv.z; a.w += tv.w;
    }
    float4 bb = ((const float4*)b2)[i % 1600];
    a.x = 1.f / (1.f + expf(-(a.x + bb.x)));
    a.y = 1.f / (1.f + expf(-(a.y + bb.y)));
    a.z = 1.f / (1.f + expf(-(a.z + bb.z)));
    a.w = 1.f / (1.f + expf(-(a.w + bb.w)));
    ((float4*)out)[i] = a;
}

// ---------------- launcher ----------------
extern "C" void kernel_launch(void* const* d_in, const int* in_sizes, int n_in,
                              void* d_out, int out_size) {
    (void)in_sizes; (void)n_in; (void)out_size;
    const float* x  = (const float*)d_in[0];
    const int*   ei = (const int*)  d_in[1];
    const float* Wg = (const float*)d_in[2];
    const float* bg = (const float*)d_in[3];
    const float* W1 = (const float*)d_in[4];
    const float* b1 = (const float*)d_in[5];
    const float* W2 = (const float*)d_in[6];
    const float* b2 = (const float*)d_in[7];
    float* out = (float*)d_out;

    float* d_h    = nullptr; cudaGetSymbolAddress((void**)&d_h,    g_h);
    float* d_gram = nullptr; cudaGetSymbolAddress((void**)&d_gram, g_gram);
    float* d_z2p  = nullptr; cudaGetSymbolAddress((void**)&d_z2p,  g_z2p);
    float* d_z2   = nullptr; cudaGetSymbolAddress((void**)&d_z2,   g_z2);
    float* d_yp   = nullptr; cudaGetSymbolAddress((void**)&d_yp,   g_yp);

    const int smem2  = 2 * (64 * 36 + 32 * 136) * 4;  // h-GEMM NT=2: 53248 B
    const int smem4s = 4 * SSTAGE * 4;                // 4-stage: 106496 B
    cudaFuncSetAttribute(k_tgemm<2, 1>, cudaFuncAttributeMaxDynamicSharedMemorySize, smem2);
    cudaFuncSetAttribute(k_tgemm4s, cudaFuncAttributeMaxDynamicSharedMemorySize, smem4s);

    k_zero<<<20, 256>>>();
    k_fill<<<640, 256>>>(ei, ei + NE);
    k_dinv<<<20, 256>>>();
    // h = x @ Wg : M=5120 (80 tiles), N=128 (NT=2), K=256 (8 chunks)
    k_tgemm<2, 1><<<dim3(1, 80, 1), 256, smem2>>>(x, Wg, d_h, TBLD, LAT, LAT, 8, 0);
    k_gather_z<<<640, 256>>>(bg);
    k_gram<<<NG, 256>>>();
    // GEMM1: [64,6400] @ [6400,12800], 100 N-tiles x splitK 3 = 300 CTAs (200 chunks)
    k_tgemm4s<<<dim3(100, 1, SK1), 128, smem4s>>>(d_gram, W1, d_z2p, N2, H1, H1,
                                                  200, (long)NG * H1);
    k_relu_c<<<800, 256>>>(b1);
    // GEMM2: [64,12800] @ [12800,6400], 50 N-tiles x splitK 6 = 300 CTAs (400 chunks)
    k_tgemm4s<<<dim3(50, 1, SK2), 128, smem4s>>>(d_z2, W2, d_yp, H1, N2, N2,
                                                 400, (long)NG * N2);
    k_sig_c<<<400, 256>>>(b2, out);
}

// round 12
// speedup vs baseline: 3.1463x; 1.0759x over previous
#include <cuda_runtime.h>
#include <cuda_fp16.h>
#include <cstdint>

#define NN 5120
#define NE 163840
#define TBLD 256
#define LAT 128
#define NG 64
#define NNEU 80
#define N2 6400
#define H1 12800

#define SK1 3     // GEMM1 split-K  (100 N-tiles x 3 = 300 CTAs)
#define SK2 6     // GEMM2 split-K  (50 N-tiles x 6 = 300 CTAs)

// ---------------- device scratch ----------------
__device__ int    g_deg[NN];
__device__ int    g_srclist[NN * 128];
__device__ float  g_dinv[NN];
__device__ float  g_h[NN * LAT];
__device__ float  g_z[NN * LAT];
__device__ __half g_gram[NG * N2];         // fp16 (A of GEMM1)
__device__ float  g_z2p[(size_t)SK1 * NG * H1];
__device__ __half g_z2[NG * H1];           // fp16 (A of GEMM2)
__device__ float  g_yp[(size_t)SK2 * NG * N2];

// ---------------- graph-side kernels ----------------
__global__ void k_zero() {
    int i = blockIdx.x * 256 + threadIdx.x;
    if (i < NN) g_deg[i] = 0;
}

__global__ void k_fill(const int* __restrict__ src, const int* __restrict__ dst) {
    int e = blockIdx.x * 256 + threadIdx.x;
    if (e >= NE) return;
    int d = dst[e];
    int slot = atomicAdd(&g_deg[d], 1);
    if (slot < 128) g_srclist[(d << 7) + slot] = src[e];
}

__global__ void k_dinv() {
    int i = blockIdx.x * 256 + threadIdx.x;
    if (i < NN) {
        int c = g_deg[i];
        g_dinv[i] = (c > 0) ? rsqrtf((float)c) : 0.0f;
    }
}

__global__ void k_gather_z(const float* __restrict__ bg) {
    int w = (blockIdx.x * blockDim.x + threadIdx.x) >> 5;
    int lane = threadIdx.x & 31;
    if (w >= NN) return;
    int cnt = g_deg[w];
    if (cnt > 128) cnt = 128;
    const int* sl = g_srclist + (w << 7);
    float4 acc = make_float4(0.f, 0.f, 0.f, 0.f);
    #pragma unroll 4
    for (int e = 0; e < cnt; e++) {
        int s = sl[e];
        float wt = g_dinv[s];
        const float4 h4 = *(const float4*)&g_h[(s << 7) + (lane << 2)];
        acc.x += wt * h4.x; acc.y += wt * h4.y;
        acc.z += wt * h4.z; acc.w += wt * h4.w;
    }
    float dv = g_dinv[w];
    float4 bb = ((const float4*)bg)[lane];
    float4 z;
    z.x = fmaxf(dv * acc.x + bb.x, 0.f);
    z.y = fmaxf(dv * acc.y + bb.y, 0.f);
    z.z = fmaxf(dv * acc.z + bb.z, 0.f);
    z.w = fmaxf(dv * acc.w + bb.w, 0.f);
    *(float4*)&g_z[(w << 7) + (lane << 2)] = z;
}

__global__ void k_gram() {
    __shared__ float zt[128][81];
    const int b = blockIdx.x;
    const int tid = threadIdx.x;
    #pragma unroll
    for (int i = 0; i < 10; i++) {
        int f = tid + i * 256;
        int row = f >> 5, k4 = f & 31;
        float4 v = *(const float4*)&g_z[((b * NNEU + row) << 7) + (k4 << 2)];
        zt[k4 * 4 + 0][row] = v.x; zt[k4 * 4 + 1][row] = v.y;
        zt[k4 * 4 + 2][row] = v.z; zt[k4 * 4 + 3][row] = v.w;
    }
    __syncthreads();
    const int tx = tid & 15, ty = tid >> 4;
    const int i0 = ty * 5, j0 = tx * 5;
    float acc[5][5];
    #pragma unroll
    for (int i = 0; i < 5; i++)
        #pragma unroll
        for (int j = 0; j < 5; j++) acc[i][j] = 0.f;
    #pragma unroll 4
    for (int k = 0; k < 128; k++) {
        float a[5], c[5];
        #pragma unroll
        for (int u = 0; u < 5; u++) { a[u] = zt[k][i0 + u]; c[u] = zt[k][j0 + u]; }
        #pragma unroll
        for (int i = 0; i < 5; i++)
            #pragma unroll
            for (int j = 0; j < 5; j++) acc[i][j] += a[i] * c[j];
    }
    __half* G = g_gram + b * N2;
    #pragma unroll
    for (int i = 0; i < 5; i++)
        #pragma unroll
        for (int j = 0; j < 5; j++)
            G[(i0 + i) * NNEU + j0 + j] = __float2half_rn(acc[i][j]);
}

// ---------------- mma helpers ----------------
__device__ __forceinline__ uint32_t smem_u32(const void* p) {
    return (uint32_t)__cvta_generic_to_shared(p);
}
__device__ __forceinline__ void cpa16(uint32_t dst, const void* src) {
    asm volatile("cp.async.cg.shared.global [%0], [%1], 16;" :: "r"(dst), "l"(src));
}
__device__ __forceinline__ uint32_t ldsu(uint32_t addr) {
    uint32_t v; asm volatile("ld.shared.b32 %0, [%1];" : "=r"(v) : "r"(addr)); return v;
}
__device__ __forceinline__ float ldsf(uint32_t addr) {
    float v; asm volatile("ld.shared.f32 %0, [%1];" : "=f"(v) : "r"(addr)); return v;
}
__device__ __forceinline__ uint32_t cvt2h(float hi, float lo) {
    uint32_t d;
    asm("cvt.rn.f16x2.f32 %0, %1, %2;" : "=r"(d) : "f"(hi), "f"(lo));
    return d;
}
// fp16 mma, fp32 accum
__device__ __forceinline__ void hmma16(float* c, const uint32_t* a, uint32_t b0, uint32_t b1) {
    asm volatile(
        "mma.sync.aligned.m16n8k16.row.col.f32.f16.f16.f32 "
        "{%0,%1,%2,%3}, {%4,%5,%6,%7}, {%8,%9}, {%0,%1,%2,%3};"
        : "+f"(c[0]), "+f"(c[1]), "+f"(c[2]), "+f"(c[3])
        : "r"(a[0]), "r"(a[1]), "r"(a[2]), "r"(a[3]), "r"(b0), "r"(b1));
}
// tf32 mma (h-GEMM only)
__device__ __forceinline__ void hmma(float* c, const uint32_t* a, uint32_t b0, uint32_t b1) {
    asm volatile(
        "mma.sync.aligned.m16n8k8.row.col.f32.tf32.tf32.f32 "
        "{%0,%1,%2,%3}, {%4,%5,%6,%7}, {%8,%9}, {%0,%1,%2,%3};"
        : "+f"(c[0]), "+f"(c[1]), "+f"(c[2]), "+f"(c[3])
        : "r"(a[0]), "r"(a[1]), "r"(a[2]), "r"(a[3]), "r"(b0), "r"(b1));
}

// ============ big-GEMM: fp16 A (native) x fp32 B (cvt in regs), 4-stage ============
// 128 threads / 4 warps, tile M=64 x N=128; warp = 4 m16 x 4 n8; K-chunk 32 (2 k16).
// A smem: half[64][40] (used cols 0..31)  -> 5120 B, banks 20g+t distinct.
// B smem: float[32][132] (used 0..127)    -> 16896 B, banks 8(2t+d)+g distinct.
// Stage 22016 B; 4 stages = 88064 B; 2 CTAs/SM.
#define FA_BYTES 5120
#define FSBW 132
#define FSTAGE_B (FA_BYTES + 32 * FSBW * 4)   // 22016 bytes

__global__ __launch_bounds__(128, 2) void k_fgemm(
    const __half* __restrict__ A, const float* __restrict__ B,
    float* __restrict__ C, int lda, int ldb, int ldc, int ctot, long csplit)
{
    extern __shared__ char smemc[];
    const int tid = threadIdx.x, wid = tid >> 5, lane = tid & 31;
    const int g = lane >> 2, t = lane & 3;
    const int n0 = blockIdx.x * 128;
    const int c0 = (int)((long)ctot * blockIdx.z / gridDim.z);
    const int c1 = (int)((long)ctot * (blockIdx.z + 1) / gridDim.z);
    const int nch = c1 - c0;
    const __half* Ab = A + (size_t)c0 * 32;
    const float* Bb = B + (size_t)c0 * 32 * ldb + n0;
    const uint32_t sb = smem_u32(smemc);
    const int nb = wid * 32;                 // warp n-base

    auto prefetch = [&](int ck) {
        uint32_t as = sb + (ck & 3) * FSTAGE_B;
        uint32_t bs = as + FA_BYTES;
        const __half* Ag = Ab + ck * 32;
        #pragma unroll
        for (int q = 0; q < 2; q++) {        // A: 64 rows x 64B = 256 x 16B
            int idx = q * 128 + tid, r = idx >> 2, f = idx & 3;
            cpa16(as + r * 80 + f * 16, Ag + (size_t)r * lda + f * 8);
        }
        const float* Bg = Bb + (size_t)ck * 32 * ldb;
        #pragma unroll
        for (int q = 0; q < 8; q++) {        // B: 32 rows x 512B = 1024 x 16B
            int idx = q * 128 + tid, r = idx >> 5, f = idx & 31;
            cpa16(bs + r * (FSBW * 4) + f * 16, Bg + (size_t)r * ldb + f * 4);
        }
        asm volatile("cp.async.commit_group;" ::: "memory");
    };

    float acc[4][4][4];
    #pragma unroll
    for (int mt = 0; mt < 4; mt++)
        #pragma unroll
        for (int nt = 0; nt < 4; nt++)
            #pragma unroll
            for (int r = 0; r < 4; r++) acc[mt][nt][r] = 0.f;

    prefetch(0); prefetch(1); prefetch(2);   // nch >= 3 always

    for (int it = 0; it < nch; it++) {
        // committed = min(it+3, nch); pending allowed = committed - (it+1)
        if (it + 3 <= nch) {
            asm volatile("cp.async.wait_group 2;" ::: "memory");
        } else if (it + 2 == nch) {
            asm volatile("cp.async.wait_group 1;" ::: "memory");
        } else {
            asm volatile("cp.async.wait_group 0;" ::: "memory");
        }
        __syncthreads();
        uint32_t as = sb + (it & 3) * FSTAGE_B;
        uint32_t bs = as + FA_BYTES;
        #pragma unroll
        for (int s = 0; s < 2; s++) {        // two k16 steps per chunk
            uint32_t a[4][4];
            #pragma unroll
            for (int mt = 0; mt < 4; mt++) {
                uint32_t r0 = as + (16 * mt + g) * 80 + s * 32 + t * 4;
                a[mt][0] = ldsu(r0);                   // (g,   2t..2t+1)
                a[mt][1] = ldsu(r0 + 8 * 80);          // (g+8, 2t..2t+1)
                a[mt][2] = ldsu(r0 + 16);              // (g,   2t+8..)
                a[mt][3] = ldsu(r0 + 8 * 80 + 16);     // (g+8, 2t+8..)
            }
            #pragma unroll
            for (int nt = 0; nt < 4; nt++) {
                uint32_t col = nb + 8 * nt + g;
                uint32_t bo = bs + ((16 * s + 2 * t) * FSBW + col) * 4;
                float f0 = ldsf(bo);
                float f1 = ldsf(bo + FSBW * 4);
                float f2 = ldsf(bo + 8 * FSBW * 4);
                float f3 = ldsf(bo + 9 * FSBW * 4);
                uint32_t b0 = cvt2h(f1, f0);           // lo = k even
                uint32_t b1 = cvt2h(f3, f2);
                #pragma unroll
                for (int mt = 0; mt < 4; mt++) hmma16(acc[mt][nt], a[mt], b0, b1);
            }
        }
        __syncthreads();
        if (it + 3 < nch) prefetch(it + 3);
    }

    float* Cb = C + (size_t)blockIdx.z * csplit + n0 + nb;
    #pragma unroll
    for (int mt = 0; mt < 4; mt++) {
        #pragma unroll
        for (int nt = 0; nt < 4; nt++) {
            float* p0 = Cb + (size_t)(16 * mt + g) * ldc + 8 * nt + 2 * t;
            p0[0] = acc[mt][nt][0]; p0[1] = acc[mt][nt][1];
            float* p1 = p0 + 8 * (size_t)ldc;
            p1[0] = acc[mt][nt][2]; p1[1] = acc[mt][nt][3];
        }
    }
}

// ============ 8-warp tf32 template (h-GEMM only), proven ============
template<int NT, int RA>
__global__ __launch_bounds__(256, 2) void k_tgemm(
    const float* __restrict__ A, const float* __restrict__ B,
    float* __restrict__ C, int lda, int ldb, int ldc, int ctot, long csplit)
{
    constexpr int BN   = 64 * NT;
    constexpr int SBW  = BN + 8;
    constexpr int ABUF = 64 * 36;
    constexpr int BUF  = ABUF + 32 * SBW;
    extern __shared__ float smem[];
    const int tid = threadIdx.x, wid = tid >> 5, lane = tid & 31;
    const int g = lane >> 2, t = lane & 3;
    const int n0 = blockIdx.x * BN;
    const int m0 = blockIdx.y * 64;
    const int c0 = (int)((long)ctot * blockIdx.z / gridDim.z);
    const int c1 = (int)((long)ctot * (blockIdx.z + 1) / gridDim.z);
    const int nch = c1 - c0;
    const float* Ab = A + (size_t)m0 * lda + (size_t)c0 * 32;
    const float* Bb = B + (size_t)c0 * 32 * ldb + n0;
    const uint32_t sb = smem_u32(smem);
    const int nbw = wid * 8 * NT;

    auto prefetch = [&](int ck, int buf) {
        uint32_t as = sb + buf * BUF * 4;
        uint32_t bs = as + ABUF * 4;
        const float* Ag = Ab + ck * 32;
        #pragma unroll
        for (int q = 0; q < 2; q++) {
            int idx = q * 256 + tid, r = idx >> 3, f = idx & 7;
            cpa16(as + (r * 36 + f * 4) * 4, Ag + (size_t)r * lda + f * 4);
        }
        const float* Bg = Bb + (size_t)ck * 32 * ldb;
        #pragma unroll
        for (int q = 0; q < 2 * NT; q++) {
            int idx = q * 256 + tid, r = idx / (16 * NT), f = idx % (16 * NT);
            cpa16(bs + (r * SBW + f * 4) * 4, Bg + (size_t)r * ldb + f * 4);
        }
        asm volatile("cp.async.commit_group;" ::: "memory");
    };

    float acc[4][NT][4];
    #pragma unroll
    for (int mt = 0; mt < 4; mt++)
        #pragma unroll
        for (int nt = 0; nt < NT; nt++)
            #pragma unroll
            for (int r = 0; r < 4; r++) acc[mt][nt][r] = 0.f;

    prefetch(0, 0);
    for (int it = 0; it < nch; it++) {
        if (it + 1 < nch) {
            prefetch(it + 1, (it + 1) & 1);
            asm volatile("cp.async.wait_group 1;" ::: "memory");
        } else {
            asm volatile("cp.async.wait_group 0;" ::: "memory");
        }
        __syncthreads();
        uint32_t as = sb + (it & 1) * BUF * 4;
        uint32_t bs = as + ABUF * 4;
        #pragma unroll
        for (int ks = 0; ks < 4; ks++) {
            uint32_t a[4][4];
            #pragma unroll
            for (int mt = 0; mt < 4; mt++) {
                uint32_t r0 = as + ((16 * mt + g) * 36 + 8 * ks + t) * 4;
                a[mt][0] = ldsu(r0);
                a[mt][1] = ldsu(r0 + 8 * 36 * 4);
                a[mt][2] = ldsu(r0 + 16);
                a[mt][3] = ldsu(r0 + 8 * 36 * 4 + 16);
                if (RA) {
                    a[mt][0] += 0x1000u; a[mt][1] += 0x1000u;
                    a[mt][2] += 0x1000u; a[mt][3] += 0x1000u;
                }
            }
            #pragma unroll
            for (int nt = 0; nt < NT; nt++) {
                uint32_t bo = bs + ((8 * ks + t) * SBW + nbw + 8 * nt + g) * 4;
                uint32_t b0 = ldsu(bo) + 0x1000u;
                uint32_t b1 = ldsu(bo + 4 * SBW * 4) + 0x1000u;
                #pragma unroll
                for (int mt = 0; mt < 4; mt++) hmma(acc[mt][nt], a[mt], b0, b1);
            }
        }
        __syncthreads();
    }

    float* Cb = C + (size_t)blockIdx.z * csplit + (size_t)m0 * ldc + n0 + nbw;
    #pragma unroll
    for (int mt = 0; mt < 4; mt++) {
        #pragma unroll
        for (int nt = 0; nt < NT; nt++) {
            float* p0 = Cb + (size_t)(16 * mt + g) * ldc + 8 * nt + 2 * t;
            p0[0] = acc[mt][nt][0]; p0[1] = acc[mt][nt][1];
            float* p1 = p0 + 8 * (size_t)ldc;
            p1[0] = acc[mt][nt][2]; p1[1] = acc[mt][nt][3];
        }
    }
}

// combine SK1 GEMM1 partials + bias, relu -> fp16 g_z2
__global__ void k_relu_c(const float* __restrict__ b1) {
    int i = blockIdx.x * 256 + threadIdx.x;          // float4 idx < 204800
    const float4* P = (const float4*)g_z2p;
    float4 a = P[i];
    #pragma unroll
    for (int s = 1; s < SK1; s++) {
        float4 tv = P[(size_t)s * 204800 + i];
        a.x += tv.x; a.y += tv.y; a.z += tv.z; a.w += tv.w;
    }
    float4 bb = ((const float4*)b1)[i % 3200];
    __half2 h0 = __floats2half2_rn(fmaxf(a.x + bb.x, 0.f), fmaxf(a.y + bb.y, 0.f));
    __half2 h1 = __floats2half2_rn(fmaxf(a.z + bb.z, 0.f), fmaxf(a.w + bb.w, 0.f));
    ((__half2*)g_z2)[2 * i]     = h0;
    ((__half2*)g_z2)[2 * i + 1] = h1;
}

// combine SK2 GEMM2 partials + bias, sigmoid -> out
__global__ void k_sig_c(const float* __restrict__ b2, float* __restrict__ out) {
    int i = blockIdx.x * 256 + threadIdx.x;          // float4 idx < 102400
    const float4* P = (const float4*)g_yp;
    float4 a = P[i];
    #pragma unroll
    for (int p = 1; p < SK2; p++) {
        float4 tv = P[(size_t)p * 102400 + i];
        a.x += tv.x; a.y += tv.y; a.z += tv.z; a.w += tv.w;
    }
    float4 bb = ((const float4*)b2)[i % 1600];
    a.x = 1.f / (1.f + expf(-(a.x + bb.x)));
    a.y = 1.f / (1.f + expf(-(a.y + bb.y)));
    a.z = 1.f / (1.f + expf(-(a.z + bb.z)));
    a.w = 1.f / (1.f + expf(-(a.w + bb.w)));
    ((float4*)out)[i] = a;
}

// ---------------- launcher ----------------
extern "C" void kernel_launch(void* const* d_in, const int* in_sizes, int n_in,
                              void* d_out, int out_size) {
    (void)in_sizes; (void)n_in; (void)out_size;
    const float* x  = (const float*)d_in[0];
    const int*   ei = (const int*)  d_in[1];
    const float* Wg = (const float*)d_in[2];
    const float* bg = (const float*)d_in[3];
    const float* W1 = (const float*)d_in[4];
    const float* b1 = (const float*)d_in[5];
    const float* W2 = (const float*)d_in[6];
    const float* b2 = (const float*)d_in[7];
    float* out = (float*)d_out;

    float*  d_h    = nullptr; cudaGetSymbolAddress((void**)&d_h,    g_h);
    __half* d_gram = nullptr; cudaGetSymbolAddress((void**)&d_gram, g_gram);
    float*  d_z2p  = nullptr; cudaGetSymbolAddress((void**)&d_z2p,  g_z2p);
    __half* d_z2   = nullptr; cudaGetSymbolAddress((void**)&d_z2,   g_z2);
    float*  d_yp   = nullptr; cudaGetSymbolAddress((void**)&d_yp,   g_yp);

    const int smem2  = 2 * (64 * 36 + 32 * 136) * 4;  // h-GEMM NT=2: 53248 B
    const int smemf  = 4 * FSTAGE_B;                  // fp16 GEMM: 88064 B
    cudaFuncSetAttribute(k_tgemm<2, 1>, cudaFuncAttributeMaxDynamicSharedMemorySize, smem2);
    cudaFuncSetAttribute(k_fgemm, cudaFuncAttributeMaxDynamicSharedMemorySize, smemf);

    k_zero<<<20, 256>>>();
    k_fill<<<640, 256>>>(ei, ei + NE);
    k_dinv<<<20, 256>>>();
    // h = x @ Wg : M=5120 (80 tiles), N=128 (NT=2), K=256 (8 chunks), tf32
    k_tgemm<2, 1><<<dim3(1, 80, 1), 256, smem2>>>(x, Wg, d_h, TBLD, LAT, LAT, 8, 0);
    k_gather_z<<<640, 256>>>(bg);
    k_gram<<<NG, 256>>>();
    // GEMM1 (fp16): [64,6400] @ [6400,12800], 100 N-tiles x splitK 3 (200 chunks)
    k_fgemm<<<dim3(100, 1, SK1), 128, smemf>>>(d_gram, W1, d_z2p, N2, H1, H1,
                                               200, (long)NG * H1);
    k_relu_c<<<800, 256>>>(b1);
    // GEMM2 (fp16): [64,12800] @ [12800,6400], 50 N-tiles x splitK 6 (400 chunks)
    k_fgemm<<<dim3(50, 1, SK2), 128, smemf>>>(d_z2, W2, d_yp, H1, N2, N2,
                                              400, (long)NG * N2);
    k_sig_c<<<400, 256>>>(b2, out);
}